// round 1
// baseline (speedup 1.0000x reference)
#include <cuda_runtime.h>
#include <math.h>

// Problem constants
#define BATCH 4
#define SEQ   2048
#define HID   1024
#define NH    16
#define HD    64
#define MTOT  (BATCH * SEQ)   // 8192

// Scratch (device globals: no runtime allocation allowed)
__device__ float g_Q [MTOT * HID];
__device__ float g_K [MTOT * HID];
__device__ float g_V [MTOT * HID];
__device__ float g_AO[MTOT * HID];

// ---------------------------------------------------------------------------
// GEMM: C[M,1024] = A[M,1024] @ W[1024,1024]^T + bias
// Row-major A and W; C[i,j] = dot(A row i, W row j)  (torch Linear semantics)
// 128x128 block tile, BK=8, 256 threads, 8x8 per-thread register tile.
// ---------------------------------------------------------------------------
__global__ __launch_bounds__(256) void gemm_xwt(
    const float* __restrict__ A,
    const float* __restrict__ W,
    const float* __restrict__ bias,
    float* __restrict__ C)
{
    constexpr int K = 1024, N = 1024;
    constexpr int BM = 128, BN = 128, BK = 8;

    __shared__ float As[BK][BM];
    __shared__ float Bs[BK][BN];

    const int tid = threadIdx.x;
    const int tx  = tid & 15;        // 0..15  -> N direction
    const int ty  = tid >> 4;        // 0..15  -> M direction
    const int row0 = blockIdx.y * BM;
    const int col0 = blockIdx.x * BN;

    float acc[8][8];
#pragma unroll
    for (int i = 0; i < 8; i++)
#pragma unroll
        for (int j = 0; j < 8; j++) acc[i][j] = 0.f;

    const int lr = tid >> 1;         // 0..127 : tile row
    const int lc = (tid & 1) * 4;    // 0 or 4 : k offset
    const float* Ap = A + (size_t)(row0 + lr) * K + lc;
    const float* Wp = W + (size_t)(col0 + lr) * K + lc;

    for (int k0 = 0; k0 < K; k0 += BK) {
        float4 a4 = *(const float4*)(Ap + k0);
        float4 b4 = *(const float4*)(Wp + k0);
        As[lc + 0][lr] = a4.x; As[lc + 1][lr] = a4.y;
        As[lc + 2][lr] = a4.z; As[lc + 3][lr] = a4.w;
        Bs[lc + 0][lr] = b4.x; Bs[lc + 1][lr] = b4.y;
        Bs[lc + 2][lr] = b4.z; Bs[lc + 3][lr] = b4.w;
        __syncthreads();

#pragma unroll
        for (int kk = 0; kk < BK; kk++) {
            float a[8], b[8];
            *(float4*)(a)     = *(const float4*)&As[kk][ty * 4];
            *(float4*)(a + 4) = *(const float4*)&As[kk][64 + ty * 4];
            *(float4*)(b)     = *(const float4*)&Bs[kk][tx * 4];
            *(float4*)(b + 4) = *(const float4*)&Bs[kk][64 + tx * 4];
#pragma unroll
            for (int i = 0; i < 8; i++)
#pragma unroll
                for (int j = 0; j < 8; j++)
                    acc[i][j] = fmaf(a[i], b[j], acc[i][j]);
        }
        __syncthreads();
    }

    // epilogue
#pragma unroll
    for (int ih = 0; ih < 2; ih++) {
#pragma unroll
        for (int i = 0; i < 4; i++) {
            const int r  = row0 + ih * 64 + ty * 4 + i;
            const int ai = ih * 4 + i;
#pragma unroll
            for (int jh = 0; jh < 2; jh++) {
                const int c = col0 + jh * 64 + tx * 4;
                float4 v;
                v.x = acc[ai][jh * 4 + 0] + bias[c + 0];
                v.y = acc[ai][jh * 4 + 1] + bias[c + 1];
                v.z = acc[ai][jh * 4 + 2] + bias[c + 2];
                v.w = acc[ai][jh * 4 + 3] + bias[c + 3];
                *(float4*)(C + (size_t)r * N + c) = v;
            }
        }
    }
}

// ---------------------------------------------------------------------------
// Fused causal flash attention, fp32.
// Block: (qi, h, b). 64-row Q tile; loop over <=qi K/V tiles of 64 rows.
// 256 threads, per-thread 4x4 S tile & 4x4 O tile, online softmax.
// Shared: Qs[d][row], Ks[d][m], Vs[m][d], Ps[m][row], stride 68 (16B aligned).
// ---------------------------------------------------------------------------
#define SSTR 68
#define ATTN_SMEM (4 * 64 * SSTR * 4)   // 69632 bytes

__global__ __launch_bounds__(256) void attn_kernel(
    const float* __restrict__ Q,
    const float* __restrict__ K,
    const float* __restrict__ V,
    float* __restrict__ O)
{
    const int qi = blockIdx.x;   // q tile (0..31)
    const int h  = blockIdx.y;
    const int b  = blockIdx.z;

    extern __shared__ float sm[];
    float* Qs = sm;                 // [64][SSTR]  (d, row)
    float* Ks = sm + 64 * SSTR;     // [64][SSTR]  (d, m)
    float* Vs = sm + 128 * SSTR;    // [64][SSTR]  (m, d)
    float* Ps = sm + 192 * SSTR;    // [64][SSTR]  (m, row)

    const int tid = threadIdx.x;
    const int tx  = tid & 15;       // m / d columns
    const int ty  = tid >> 4;       // q rows

    const float* Qb = Q + ((size_t)b * SEQ + qi * 64) * HID + h * HD;

    // Load Q tile transposed: Qs[d][row]
    for (int t = tid; t < 64 * 16; t += 256) {
        const int r  = t >> 4;
        const int dq = (t & 15) * 4;
        float4 v = *(const float4*)(Qb + (size_t)r * HID + dq);
        Qs[(dq + 0) * SSTR + r] = v.x;
        Qs[(dq + 1) * SSTR + r] = v.y;
        Qs[(dq + 2) * SSTR + r] = v.z;
        Qs[(dq + 3) * SSTR + r] = v.w;
    }

    float m_i[4], l_i[4], o[4][4];
#pragma unroll
    for (int i = 0; i < 4; i++) {
        m_i[i] = -1e30f; l_i[i] = 0.f;
#pragma unroll
        for (int j = 0; j < 4; j++) o[i][j] = 0.f;
    }
    __syncthreads();

    for (int kt = 0; kt <= qi; kt++) {
        const float* Kb = K + ((size_t)b * SEQ + kt * 64) * HID + h * HD;
        const float* Vb = V + ((size_t)b * SEQ + kt * 64) * HID + h * HD;
        // Load K (transposed) and V (natural) tiles
        for (int t = tid; t < 64 * 16; t += 256) {
            const int r  = t >> 4;
            const int dq = (t & 15) * 4;
            float4 kv = *(const float4*)(Kb + (size_t)r * HID + dq);
            Ks[(dq + 0) * SSTR + r] = kv.x;
            Ks[(dq + 1) * SSTR + r] = kv.y;
            Ks[(dq + 2) * SSTR + r] = kv.z;
            Ks[(dq + 3) * SSTR + r] = kv.w;
            float4 vv = *(const float4*)(Vb + (size_t)r * HID + dq);
            *(float4*)&Vs[r * SSTR + dq] = vv;
        }
        __syncthreads();

        // S = Q K^T  (4x4 per thread)
        float s[4][4];
#pragma unroll
        for (int i = 0; i < 4; i++)
#pragma unroll
            for (int j = 0; j < 4; j++) s[i][j] = 0.f;

#pragma unroll 8
        for (int d = 0; d < 64; d++) {
            float qa[4], kb[4];
            *(float4*)qa = *(const float4*)&Qs[d * SSTR + ty * 4];
            *(float4*)kb = *(const float4*)&Ks[d * SSTR + tx * 4];
#pragma unroll
            for (int i = 0; i < 4; i++)
#pragma unroll
                for (int j = 0; j < 4; j++)
                    s[i][j] = fmaf(qa[i], kb[j], s[i][j]);
        }

        const bool diag = (kt == qi);
#pragma unroll
        for (int i = 0; i < 4; i++) {
            const int rloc = ty * 4 + i;
#pragma unroll
            for (int j = 0; j < 4; j++) {
                s[i][j] *= 0.125f;                       // 1/sqrt(64)
                if (diag && (tx * 4 + j) > rloc) s[i][j] = -1e30f;
            }
        }

        // online softmax update
#pragma unroll
        for (int i = 0; i < 4; i++) {
            float mx = fmaxf(fmaxf(s[i][0], s[i][1]), fmaxf(s[i][2], s[i][3]));
#pragma unroll
            for (int off = 1; off < 16; off <<= 1)
                mx = fmaxf(mx, __shfl_xor_sync(0xffffffffu, mx, off));
            const float m_new = fmaxf(m_i[i], mx);
            const float alpha = __expf(m_i[i] - m_new);
            float sum = 0.f;
#pragma unroll
            for (int j = 0; j < 4; j++) {
                const float p = __expf(s[i][j] - m_new);
                s[i][j] = p;
                sum += p;
            }
#pragma unroll
            for (int off = 1; off < 16; off <<= 1)
                sum += __shfl_xor_sync(0xffffffffu, sum, off);
            l_i[i] = l_i[i] * alpha + sum;
            m_i[i] = m_new;
#pragma unroll
            for (int j = 0; j < 4; j++) o[i][j] *= alpha;
        }

        // write P transposed: Ps[m][row]
#pragma unroll
        for (int j = 0; j < 4; j++)
#pragma unroll
            for (int i = 0; i < 4; i++)
                Ps[(tx * 4 + j) * SSTR + (ty * 4 + i)] = s[i][j];
        __syncthreads();

        // O += P @ V
#pragma unroll 8
        for (int m = 0; m < 64; m++) {
            float pa[4], vb[4];
            *(float4*)pa = *(const float4*)&Ps[m * SSTR + ty * 4];
            *(float4*)vb = *(const float4*)&Vs[m * SSTR + tx * 4];
#pragma unroll
            for (int i = 0; i < 4; i++)
#pragma unroll
                for (int j = 0; j < 4; j++)
                    o[i][j] = fmaf(pa[i], vb[j], o[i][j]);
        }
        __syncthreads();
    }

    // epilogue: O /= l, store
    float* Ob = O + ((size_t)b * SEQ + qi * 64) * HID + h * HD;
#pragma unroll
    for (int i = 0; i < 4; i++) {
        const float inv = 1.f / l_i[i];
        float4 v;
        v.x = o[i][0] * inv; v.y = o[i][1] * inv;
        v.z = o[i][2] * inv; v.w = o[i][3] * inv;
        *(float4*)(Ob + (size_t)(ty * 4 + i) * HID + tx * 4) = v;
    }
}

// ---------------------------------------------------------------------------
extern "C" void kernel_launch(void* const* d_in, const int* in_sizes, int n_in,
                              void* d_out, int out_size)
{
    const float* query = (const float*)d_in[0];
    const float* key   = (const float*)d_in[1];
    const float* val   = (const float*)d_in[2];
    // d_in[3] = attn_mask (tril causal) — implemented directly in attn_kernel
    const float* Wq = (const float*)d_in[4];
    const float* bq = (const float*)d_in[5];
    const float* Wk = (const float*)d_in[6];
    const float* bk = (const float*)d_in[7];
    const float* Wv = (const float*)d_in[8];
    const float* bv = (const float*)d_in[9];
    const float* Wo = (const float*)d_in[10];
    const float* bo = (const float*)d_in[11];
    float* out = (float*)d_out;

    void *pQ, *pK, *pV, *pAO;
    cudaGetSymbolAddress(&pQ,  g_Q);
    cudaGetSymbolAddress(&pK,  g_K);
    cudaGetSymbolAddress(&pV,  g_V);
    cudaGetSymbolAddress(&pAO, g_AO);

    cudaFuncSetAttribute(attn_kernel,
                         cudaFuncAttributeMaxDynamicSharedMemorySize,
                         ATTN_SMEM);

    const dim3 ggrid(HID / 128, MTOT / 128);   // (8, 64)
    gemm_xwt<<<ggrid, 256>>>(query, Wq, bq, (float*)pQ);
    gemm_xwt<<<ggrid, 256>>>(key,   Wk, bk, (float*)pK);
    gemm_xwt<<<ggrid, 256>>>(val,   Wv, bv, (float*)pV);

    const dim3 agrid(SEQ / 64, NH, BATCH);      // (32, 16, 4)
    attn_kernel<<<agrid, 256, ATTN_SMEM>>>((const float*)pQ, (const float*)pK,
                                           (const float*)pV, (float*)pAO);

    gemm_xwt<<<ggrid, 256>>>((const float*)pAO, Wo, bo, out);
}

// round 2
// speedup vs baseline: 1.4735x; 1.4735x over previous
#include <cuda_runtime.h>
#include <math.h>

// Problem constants
#define BATCH 4
#define SEQ   2048
#define HID   1024
#define NH    16
#define HD    64
#define MTOT  (BATCH * SEQ)   // 8192

// Scratch (device globals: no runtime allocation allowed)
__device__ float g_Q [MTOT * HID];
__device__ float g_K [MTOT * HID];
__device__ float g_V [MTOT * HID];
__device__ float g_AO[MTOT * HID];

// ---------------------------------------------------------------------------
// TF32 tensor-core GEMM: C[M,1024] = A[M,1024] @ W[1024,1024]^T + bias
// (torch Linear). 128x128x16 block tile, 8 warps (2x4), warp tile 64x32,
// mma.sync m16n8k8 tf32. Smem stride 136 -> conflict-free fragment LDS.
// ---------------------------------------------------------------------------
#define GK   1024
#define GN   1024
#define SSTRG 136   // smem row stride (floats); 136%32=8 -> 8*tig+grp distinct banks

__device__ __forceinline__ unsigned f2tf32(float f) {
    unsigned u;
    asm volatile("cvt.rna.tf32.f32 %0, %1;" : "=r"(u) : "f"(f));
    return u;
}

__device__ __forceinline__ void mma_tf32(float* d, const unsigned* a, const unsigned* b) {
    asm volatile(
        "mma.sync.aligned.m16n8k8.row.col.f32.tf32.tf32.f32 "
        "{%0,%1,%2,%3}, {%4,%5,%6,%7}, {%8,%9}, {%0,%1,%2,%3};\n"
        : "+f"(d[0]), "+f"(d[1]), "+f"(d[2]), "+f"(d[3])
        : "r"(a[0]), "r"(a[1]), "r"(a[2]), "r"(a[3]),
          "r"(b[0]), "r"(b[1]));
}

__global__ __launch_bounds__(256) void gemm_tf32(
    const float* __restrict__ A,
    const float* __restrict__ W,
    const float* __restrict__ bias,
    float* __restrict__ C)
{
    __shared__ unsigned As[16 * SSTRG];   // [k][m]
    __shared__ unsigned Bs[16 * SSTRG];   // [k][n]

    const int tid  = threadIdx.x;
    const int lane = tid & 31;
    const int wid  = tid >> 5;
    const int wr   = wid >> 2;           // 0..1 : 64-row chunk
    const int wc   = wid & 3;            // 0..3 : 32-col chunk
    const int tig  = lane & 3;           // threadID_in_group
    const int grp  = lane >> 2;          // groupID

    const int row0 = blockIdx.y * 128;
    const int col0 = blockIdx.x * 128;

    float acc[4][4][4];
#pragma unroll
    for (int mi = 0; mi < 4; mi++)
#pragma unroll
        for (int ni = 0; ni < 4; ni++)
#pragma unroll
            for (int q = 0; q < 4; q++) acc[mi][ni][q] = 0.f;

    // global-load mapping: 256 threads, each owns (row = tid>>1, k-half = (tid&1)*8)
    const int glr = tid >> 1;            // 0..127
    const int glk = (tid & 1) * 8;       // 0 or 8
    const float* Ap = A + (size_t)(row0 + glr) * GK + glk;
    const float* Wp = W + (size_t)(col0 + glr) * GK + glk;

    for (int k0 = 0; k0 < GK; k0 += 16) {
        float4 av0 = *(const float4*)(Ap + k0);
        float4 av1 = *(const float4*)(Ap + k0 + 4);
        float4 bv0 = *(const float4*)(Wp + k0);
        float4 bv1 = *(const float4*)(Wp + k0 + 4);

        As[(glk + 0) * SSTRG + glr] = f2tf32(av0.x);
        As[(glk + 1) * SSTRG + glr] = f2tf32(av0.y);
        As[(glk + 2) * SSTRG + glr] = f2tf32(av0.z);
        As[(glk + 3) * SSTRG + glr] = f2tf32(av0.w);
        As[(glk + 4) * SSTRG + glr] = f2tf32(av1.x);
        As[(glk + 5) * SSTRG + glr] = f2tf32(av1.y);
        As[(glk + 6) * SSTRG + glr] = f2tf32(av1.z);
        As[(glk + 7) * SSTRG + glr] = f2tf32(av1.w);

        Bs[(glk + 0) * SSTRG + glr] = f2tf32(bv0.x);
        Bs[(glk + 1) * SSTRG + glr] = f2tf32(bv0.y);
        Bs[(glk + 2) * SSTRG + glr] = f2tf32(bv0.z);
        Bs[(glk + 3) * SSTRG + glr] = f2tf32(bv0.w);
        Bs[(glk + 4) * SSTRG + glr] = f2tf32(bv1.x);
        Bs[(glk + 5) * SSTRG + glr] = f2tf32(bv1.y);
        Bs[(glk + 6) * SSTRG + glr] = f2tf32(bv1.z);
        Bs[(glk + 7) * SSTRG + glr] = f2tf32(bv1.w);
        __syncthreads();

#pragma unroll
        for (int kk = 0; kk < 16; kk += 8) {
            unsigned af[4][4], bf[4][2];
#pragma unroll
            for (int mi = 0; mi < 4; mi++) {
                const int r = wr * 64 + mi * 16 + grp;
                af[mi][0] = As[(kk + tig) * SSTRG + r];
                af[mi][1] = As[(kk + tig) * SSTRG + r + 8];
                af[mi][2] = As[(kk + tig + 4) * SSTRG + r];
                af[mi][3] = As[(kk + tig + 4) * SSTRG + r + 8];
            }
#pragma unroll
            for (int ni = 0; ni < 4; ni++) {
                const int c = wc * 32 + ni * 8 + grp;
                bf[ni][0] = Bs[(kk + tig) * SSTRG + c];
                bf[ni][1] = Bs[(kk + tig + 4) * SSTRG + c];
            }
#pragma unroll
            for (int mi = 0; mi < 4; mi++)
#pragma unroll
                for (int ni = 0; ni < 4; ni++)
                    mma_tf32(acc[mi][ni], af[mi], bf[ni]);
        }
        __syncthreads();
    }

    // epilogue: bias add, float2 stores
#pragma unroll
    for (int mi = 0; mi < 4; mi++) {
        const int r = row0 + wr * 64 + mi * 16 + grp;
#pragma unroll
        for (int ni = 0; ni < 4; ni++) {
            const int c = col0 + wc * 32 + ni * 8 + tig * 2;
            const float b0 = bias[c], b1 = bias[c + 1];
            float2 v0, v1;
            v0.x = acc[mi][ni][0] + b0;
            v0.y = acc[mi][ni][1] + b1;
            v1.x = acc[mi][ni][2] + b0;
            v1.y = acc[mi][ni][3] + b1;
            *(float2*)(C + (size_t)r * GN + c)       = v0;
            *(float2*)(C + (size_t)(r + 8) * GN + c) = v1;
        }
    }
}

// ---------------------------------------------------------------------------
// Fused causal flash attention, fp32 (unchanged from R1).
// ---------------------------------------------------------------------------
#define SSTR 68
#define ATTN_SMEM (4 * 64 * SSTR * 4)   // 69632 bytes

__global__ __launch_bounds__(256) void attn_kernel(
    const float* __restrict__ Q,
    const float* __restrict__ K,
    const float* __restrict__ V,
    float* __restrict__ O)
{
    const int qi = blockIdx.x;
    const int h  = blockIdx.y;
    const int b  = blockIdx.z;

    extern __shared__ float sm[];
    float* Qs = sm;
    float* Ks = sm + 64 * SSTR;
    float* Vs = sm + 128 * SSTR;
    float* Ps = sm + 192 * SSTR;

    const int tid = threadIdx.x;
    const int tx  = tid & 15;
    const int ty  = tid >> 4;

    const float* Qb = Q + ((size_t)b * SEQ + qi * 64) * HID + h * HD;

    for (int t = tid; t < 64 * 16; t += 256) {
        const int r  = t >> 4;
        const int dq = (t & 15) * 4;
        float4 v = *(const float4*)(Qb + (size_t)r * HID + dq);
        Qs[(dq + 0) * SSTR + r] = v.x;
        Qs[(dq + 1) * SSTR + r] = v.y;
        Qs[(dq + 2) * SSTR + r] = v.z;
        Qs[(dq + 3) * SSTR + r] = v.w;
    }

    float m_i[4], l_i[4], o[4][4];
#pragma unroll
    for (int i = 0; i < 4; i++) {
        m_i[i] = -1e30f; l_i[i] = 0.f;
#pragma unroll
        for (int j = 0; j < 4; j++) o[i][j] = 0.f;
    }
    __syncthreads();

    for (int kt = 0; kt <= qi; kt++) {
        const float* Kb = K + ((size_t)b * SEQ + kt * 64) * HID + h * HD;
        const float* Vb = V + ((size_t)b * SEQ + kt * 64) * HID + h * HD;
        for (int t = tid; t < 64 * 16; t += 256) {
            const int r  = t >> 4;
            const int dq = (t & 15) * 4;
            float4 kv = *(const float4*)(Kb + (size_t)r * HID + dq);
            Ks[(dq + 0) * SSTR + r] = kv.x;
            Ks[(dq + 1) * SSTR + r] = kv.y;
            Ks[(dq + 2) * SSTR + r] = kv.z;
            Ks[(dq + 3) * SSTR + r] = kv.w;
            float4 vv = *(const float4*)(Vb + (size_t)r * HID + dq);
            *(float4*)&Vs[r * SSTR + dq] = vv;
        }
        __syncthreads();

        float s[4][4];
#pragma unroll
        for (int i = 0; i < 4; i++)
#pragma unroll
            for (int j = 0; j < 4; j++) s[i][j] = 0.f;

#pragma unroll 8
        for (int d = 0; d < 64; d++) {
            float qa[4], kb[4];
            *(float4*)qa = *(const float4*)&Qs[d * SSTR + ty * 4];
            *(float4*)kb = *(const float4*)&Ks[d * SSTR + tx * 4];
#pragma unroll
            for (int i = 0; i < 4; i++)
#pragma unroll
                for (int j = 0; j < 4; j++)
                    s[i][j] = fmaf(qa[i], kb[j], s[i][j]);
        }

        const bool diag = (kt == qi);
#pragma unroll
        for (int i = 0; i < 4; i++) {
            const int rloc = ty * 4 + i;
#pragma unroll
            for (int j = 0; j < 4; j++) {
                s[i][j] *= 0.125f;
                if (diag && (tx * 4 + j) > rloc) s[i][j] = -1e30f;
            }
        }

#pragma unroll
        for (int i = 0; i < 4; i++) {
            float mx = fmaxf(fmaxf(s[i][0], s[i][1]), fmaxf(s[i][2], s[i][3]));
#pragma unroll
            for (int off = 1; off < 16; off <<= 1)
                mx = fmaxf(mx, __shfl_xor_sync(0xffffffffu, mx, off));
            const float m_new = fmaxf(m_i[i], mx);
            const float alpha = __expf(m_i[i] - m_new);
            float sum = 0.f;
#pragma unroll
            for (int j = 0; j < 4; j++) {
                const float p = __expf(s[i][j] - m_new);
                s[i][j] = p;
                sum += p;
            }
#pragma unroll
            for (int off = 1; off < 16; off <<= 1)
                sum += __shfl_xor_sync(0xffffffffu, sum, off);
            l_i[i] = l_i[i] * alpha + sum;
            m_i[i] = m_new;
#pragma unroll
            for (int j = 0; j < 4; j++) o[i][j] *= alpha;
        }

#pragma unroll
        for (int j = 0; j < 4; j++)
#pragma unroll
            for (int i = 0; i < 4; i++)
                Ps[(tx * 4 + j) * SSTR + (ty * 4 + i)] = s[i][j];
        __syncthreads();

#pragma unroll 8
        for (int m = 0; m < 64; m++) {
            float pa[4], vb[4];
            *(float4*)pa = *(const float4*)&Ps[m * SSTR + ty * 4];
            *(float4*)vb = *(const float4*)&Vs[m * SSTR + tx * 4];
#pragma unroll
            for (int i = 0; i < 4; i++)
#pragma unroll
                for (int j = 0; j < 4; j++)
                    o[i][j] = fmaf(pa[i], vb[j], o[i][j]);
        }
        __syncthreads();
    }

    float* Ob = O + ((size_t)b * SEQ + qi * 64) * HID + h * HD;
#pragma unroll
    for (int i = 0; i < 4; i++) {
        const float inv = 1.f / l_i[i];
        float4 v;
        v.x = o[i][0] * inv; v.y = o[i][1] * inv;
        v.z = o[i][2] * inv; v.w = o[i][3] * inv;
        *(float4*)(Ob + (size_t)(ty * 4 + i) * HID + tx * 4) = v;
    }
}

// ---------------------------------------------------------------------------
extern "C" void kernel_launch(void* const* d_in, const int* in_sizes, int n_in,
                              void* d_out, int out_size)
{
    const float* query = (const float*)d_in[0];
    const float* key   = (const float*)d_in[1];
    const float* val   = (const float*)d_in[2];
    // d_in[3] = attn_mask (tril causal) — implemented directly in attn_kernel
    const float* Wq = (const float*)d_in[4];
    const float* bq = (const float*)d_in[5];
    const float* Wk = (const float*)d_in[6];
    const float* bk = (const float*)d_in[7];
    const float* Wv = (const float*)d_in[8];
    const float* bv = (const float*)d_in[9];
    const float* Wo = (const float*)d_in[10];
    const float* bo = (const float*)d_in[11];
    float* out = (float*)d_out;

    void *pQ, *pK, *pV, *pAO;
    cudaGetSymbolAddress(&pQ,  g_Q);
    cudaGetSymbolAddress(&pK,  g_K);
    cudaGetSymbolAddress(&pV,  g_V);
    cudaGetSymbolAddress(&pAO, g_AO);

    cudaFuncSetAttribute(attn_kernel,
                         cudaFuncAttributeMaxDynamicSharedMemorySize,
                         ATTN_SMEM);

    const dim3 ggrid(HID / 128, MTOT / 128);   // (8, 64)
    gemm_tf32<<<ggrid, 256>>>(query, Wq, bq, (float*)pQ);
    gemm_tf32<<<ggrid, 256>>>(key,   Wk, bk, (float*)pK);
    gemm_tf32<<<ggrid, 256>>>(val,   Wv, bv, (float*)pV);

    const dim3 agrid(SEQ / 64, NH, BATCH);      // (32, 16, 4)
    attn_kernel<<<agrid, 256, ATTN_SMEM>>>((const float*)pQ, (const float*)pK,
                                           (const float*)pV, (float*)pAO);

    gemm_tf32<<<ggrid, 256>>>((const float*)pAO, Wo, bo, out);
}

// round 3
// speedup vs baseline: 2.0349x; 1.3810x over previous
#include <cuda_runtime.h>
#include <math.h>

// Problem constants
#define BATCH 4
#define SEQ   2048
#define HID   1024
#define NH    16
#define HD    64
#define MTOT  (BATCH * SEQ)   // 8192

// Scratch (device globals: no runtime allocation allowed)
__device__ float g_Q [MTOT * HID];
__device__ float g_K [MTOT * HID];
__device__ float g_V [MTOT * HID];
__device__ float g_AO[MTOT * HID];

__device__ __forceinline__ unsigned f2tf32(float f) {
    unsigned u;
    asm volatile("cvt.rna.tf32.f32 %0, %1;" : "=r"(u) : "f"(f));
    return u;
}

__device__ __forceinline__ void mma_tf32(float* d, const unsigned* a, const unsigned* b) {
    asm volatile(
        "mma.sync.aligned.m16n8k8.row.col.f32.tf32.tf32.f32 "
        "{%0,%1,%2,%3}, {%4,%5,%6,%7}, {%8,%9}, {%0,%1,%2,%3};\n"
        : "+f"(d[0]), "+f"(d[1]), "+f"(d[2]), "+f"(d[3])
        : "r"(a[0]), "r"(a[1]), "r"(a[2]), "r"(a[3]),
          "r"(b[0]), "r"(b[1]));
}

// ---------------------------------------------------------------------------
// TF32 GEMM v2: C[M,1024] = A[M,1024] @ W[1024,1024]^T + bias
// 128x128x16 tile, 8 warps (2x4), double-buffered smem pipeline.
// Natural layout As[m][k], Bs[n][k] with stride 24 -> conflict-free frags.
// ---------------------------------------------------------------------------
#define GK   1024
#define GN   1024
#define GSTR 24
#define GEMM_SMEM (4 * 128 * GSTR * 4)   // 49152 bytes

__global__ __launch_bounds__(256, 2) void gemm_tf32(
    const float* __restrict__ A,
    const float* __restrict__ W,
    const float* __restrict__ bias,
    float* __restrict__ C)
{
    extern __shared__ unsigned gsm[];
    unsigned* Abuf[2] = { gsm,            gsm + 128 * GSTR };
    unsigned* Bbuf[2] = { gsm + 2 * 128 * GSTR, gsm + 3 * 128 * GSTR };

    const int tid  = threadIdx.x;
    const int lane = tid & 31;
    const int wid  = tid >> 5;
    const int wr   = wid >> 2;           // 0..1 : 64-row chunk
    const int wc   = wid & 3;            // 0..3 : 32-col chunk
    const int tig  = lane & 3;
    const int grp  = lane >> 2;

    const int row0 = blockIdx.y * 128;
    const int col0 = blockIdx.x * 128;

    float acc[4][4][4];
#pragma unroll
    for (int mi = 0; mi < 4; mi++)
#pragma unroll
        for (int ni = 0; ni < 4; ni++)
#pragma unroll
            for (int q = 0; q < 4; q++) acc[mi][ni][q] = 0.f;

    const int glr = tid >> 1;            // 0..127
    const int glk = (tid & 1) * 8;       // 0 or 8
    const float* Ap = A + (size_t)(row0 + glr) * GK + glk;
    const float* Wp = W + (size_t)(col0 + glr) * GK + glk;
    const int sbase = glr * GSTR + glk;

    // prolog: load + store k-chunk 0
    float4 na0 = *(const float4*)(Ap);
    float4 na1 = *(const float4*)(Ap + 4);
    float4 nb0 = *(const float4*)(Wp);
    float4 nb1 = *(const float4*)(Wp + 4);
    {
        uint4 u0 = { f2tf32(na0.x), f2tf32(na0.y), f2tf32(na0.z), f2tf32(na0.w) };
        uint4 u1 = { f2tf32(na1.x), f2tf32(na1.y), f2tf32(na1.z), f2tf32(na1.w) };
        *(uint4*)&Abuf[0][sbase]     = u0;
        *(uint4*)&Abuf[0][sbase + 4] = u1;
        uint4 w0 = { f2tf32(nb0.x), f2tf32(nb0.y), f2tf32(nb0.z), f2tf32(nb0.w) };
        uint4 w1 = { f2tf32(nb1.x), f2tf32(nb1.y), f2tf32(nb1.z), f2tf32(nb1.w) };
        *(uint4*)&Bbuf[0][sbase]     = w0;
        *(uint4*)&Bbuf[0][sbase + 4] = w1;
    }
    __syncthreads();

    for (int it = 0; it < 64; it++) {
        const int cur = it & 1;
        const unsigned* Ac = Abuf[cur];
        const unsigned* Bc = Bbuf[cur];

        if (it < 63) {
            const float* ap = Ap + (it + 1) * 16;
            const float* wp = Wp + (it + 1) * 16;
            na0 = *(const float4*)(ap);
            na1 = *(const float4*)(ap + 4);
            nb0 = *(const float4*)(wp);
            nb1 = *(const float4*)(wp + 4);
        }

#pragma unroll
        for (int kk = 0; kk < 16; kk += 8) {
            unsigned af[4][4], bf[4][2];
#pragma unroll
            for (int mi = 0; mi < 4; mi++) {
                const int ab = (wr * 64 + mi * 16 + grp) * GSTR + kk + tig;
                af[mi][0] = Ac[ab];
                af[mi][1] = Ac[ab + 8 * GSTR];
                af[mi][2] = Ac[ab + 4];
                af[mi][3] = Ac[ab + 8 * GSTR + 4];
            }
#pragma unroll
            for (int ni = 0; ni < 4; ni++) {
                const int bb = (wc * 32 + ni * 8 + grp) * GSTR + kk + tig;
                bf[ni][0] = Bc[bb];
                bf[ni][1] = Bc[bb + 4];
            }
#pragma unroll
            for (int mi = 0; mi < 4; mi++)
#pragma unroll
                for (int ni = 0; ni < 4; ni++)
                    mma_tf32(acc[mi][ni], af[mi], bf[ni]);
        }

        if (it < 63) {
            unsigned* An = Abuf[cur ^ 1];
            unsigned* Bn = Bbuf[cur ^ 1];
            uint4 u0 = { f2tf32(na0.x), f2tf32(na0.y), f2tf32(na0.z), f2tf32(na0.w) };
            uint4 u1 = { f2tf32(na1.x), f2tf32(na1.y), f2tf32(na1.z), f2tf32(na1.w) };
            *(uint4*)&An[sbase]     = u0;
            *(uint4*)&An[sbase + 4] = u1;
            uint4 w0 = { f2tf32(nb0.x), f2tf32(nb0.y), f2tf32(nb0.z), f2tf32(nb0.w) };
            uint4 w1 = { f2tf32(nb1.x), f2tf32(nb1.y), f2tf32(nb1.z), f2tf32(nb1.w) };
            *(uint4*)&Bn[sbase]     = w0;
            *(uint4*)&Bn[sbase + 4] = w1;
        }
        __syncthreads();
    }

    // epilogue: bias add, float2 stores
#pragma unroll
    for (int mi = 0; mi < 4; mi++) {
        const int r = row0 + wr * 64 + mi * 16 + grp;
#pragma unroll
        for (int ni = 0; ni < 4; ni++) {
            const int c = col0 + wc * 32 + ni * 8 + tig * 2;
            const float b0 = bias[c], b1 = bias[c + 1];
            float2 v0, v1;
            v0.x = acc[mi][ni][0] + b0;
            v0.y = acc[mi][ni][1] + b1;
            v1.x = acc[mi][ni][2] + b0;
            v1.y = acc[mi][ni][3] + b1;
            *(float2*)(C + (size_t)r * GN + c)       = v0;
            *(float2*)(C + (size_t)(r + 8) * GN + c) = v1;
        }
    }
}

// ---------------------------------------------------------------------------
// TF32 tensor-core causal flash attention.
// BM=128 q-rows per block, BN=64 key tile, 8 warps, 256 threads.
// S phase:  S = Q K^T    (warp owns 16 q-rows x 64 keys; row-local softmax)
// O phase:  O^T = V^T P^T (warp owns 32 d x 32 q)  -> all operands natural
// layout, conflict-free smem (stride 72 == 8 mod 32).
// ---------------------------------------------------------------------------
#define ASTR 72
#define QS_OFF 0                        // Qs[128][72] tf32
#define KS_OFF (128 * ASTR)             // Ks[64][72]
#define VS_OFF (KS_OFF + 64 * ASTR)     // Vs[64][72]
#define PS_OFF (VS_OFF + 64 * ASTR)     // Ps[128][72] tf32
#define AL_OFF (PS_OFF + 128 * ASTR)    // alpha / 1-over-l [128] floats
#define ATT_SMEM ((AL_OFF + 128) * 4)   // 111104 bytes

__global__ __launch_bounds__(256, 2) void attn_tc(
    const float* __restrict__ Q,
    const float* __restrict__ K,
    const float* __restrict__ V,
    float* __restrict__ O)
{
    extern __shared__ unsigned sm[];
    unsigned* Qs = sm + QS_OFF;
    unsigned* Ks = sm + KS_OFF;
    unsigned* Vs = sm + VS_OFF;
    unsigned* Ps = sm + PS_OFF;
    float*    alp = (float*)(sm + AL_OFF);

    const int tid  = threadIdx.x;
    const int lane = tid & 31;
    const int wid  = tid >> 5;
    const int tig  = lane & 3;
    const int grp  = lane >> 2;

    const int qi = (gridDim.x - 1) - blockIdx.x;   // heavy blocks first
    const int h  = blockIdx.y;
    const int b  = blockIdx.z;

    const int srow = wid * 16;          // S-phase q rows for this warp
    const int dch  = (wid & 1) * 32;    // O-phase d chunk
    const int qch  = (wid >> 1) * 32;   // O-phase q chunk

    // Load Q tile (128 x 64) -> Qs[q][d] tf32
    const float* Qb = Q + ((size_t)b * SEQ + qi * 128) * HID + h * HD;
    for (int t = tid; t < 2048; t += 256) {
        const int r  = t >> 4;
        const int c4 = (t & 15) * 4;
        float4 v = *(const float4*)(Qb + (size_t)r * HID + c4);
        uint4 u = { f2tf32(v.x), f2tf32(v.y), f2tf32(v.z), f2tf32(v.w) };
        *(uint4*)&Qs[r * ASTR + c4] = u;
    }

    float m_i[2] = { -1e30f, -1e30f };
    float l_i[2] = { 0.f, 0.f };
    float o[2][4][4];
#pragma unroll
    for (int mi = 0; mi < 2; mi++)
#pragma unroll
        for (int ni = 0; ni < 4; ni++)
#pragma unroll
            for (int q = 0; q < 4; q++) o[mi][ni][q] = 0.f;

    const int ktmax = 2 * qi + 1;
    for (int kt = 0; kt <= ktmax; kt++) {
        __syncthreads();   // protects Ks/Vs/Ps/alp reuse

        // Load K and V tiles (64 x 64) -> natural [key][d] tf32
        const float* Kb = K + ((size_t)b * SEQ + kt * 64) * HID + h * HD;
        const float* Vb = V + ((size_t)b * SEQ + kt * 64) * HID + h * HD;
        for (int t = tid; t < 1024; t += 256) {
            const int r  = t >> 4;
            const int c4 = (t & 15) * 4;
            float4 kv = *(const float4*)(Kb + (size_t)r * HID + c4);
            uint4 uk = { f2tf32(kv.x), f2tf32(kv.y), f2tf32(kv.z), f2tf32(kv.w) };
            *(uint4*)&Ks[r * ASTR + c4] = uk;
            float4 vv = *(const float4*)(Vb + (size_t)r * HID + c4);
            uint4 uv = { f2tf32(vv.x), f2tf32(vv.y), f2tf32(vv.z), f2tf32(vv.w) };
            *(uint4*)&Vs[r * ASTR + c4] = uv;
        }
        __syncthreads();

        // ---- S phase: S = Q K^T (16 x 64 per warp) ----
        float s[8][4];
#pragma unroll
        for (int ni = 0; ni < 8; ni++)
#pragma unroll
            for (int q = 0; q < 4; q++) s[ni][q] = 0.f;

#pragma unroll
        for (int kk = 0; kk < 8; kk++) {
            unsigned a[4];
            const int ab = (srow + grp) * ASTR + kk * 8 + tig;
            a[0] = Qs[ab];
            a[1] = Qs[ab + 8 * ASTR];
            a[2] = Qs[ab + 4];
            a[3] = Qs[ab + 8 * ASTR + 4];
#pragma unroll
            for (int ni = 0; ni < 8; ni++) {
                const int bb = (ni * 8 + grp) * ASTR + kk * 8 + tig;
                unsigned bf[2] = { Ks[bb], Ks[bb + 4] };
                mma_tf32(s[ni], a, bf);
            }
        }

        // scale + causal mask
        const int row0 = qi * 128 + srow + grp;
        if (kt >= 2 * qi) {
#pragma unroll
            for (int ni = 0; ni < 8; ni++) {
                const int c0 = kt * 64 + ni * 8 + tig * 2;
#pragma unroll
                for (int q = 0; q < 4; q++) {
                    const int row = (q < 2) ? row0 : row0 + 8;
                    const int col = c0 + (q & 1);
                    s[ni][q] = (col > row) ? -1e30f : s[ni][q] * 0.125f;
                }
            }
        } else {
#pragma unroll
            for (int ni = 0; ni < 8; ni++)
#pragma unroll
                for (int q = 0; q < 4; q++) s[ni][q] *= 0.125f;
        }

        // online softmax (2 rows per thread; quad shfl reduction)
#pragma unroll
        for (int r = 0; r < 2; r++) {
            const int q0 = 2 * r, q1 = 2 * r + 1;
            float mx = -1e30f;
#pragma unroll
            for (int ni = 0; ni < 8; ni++)
                mx = fmaxf(mx, fmaxf(s[ni][q0], s[ni][q1]));
            mx = fmaxf(mx, __shfl_xor_sync(0xffffffffu, mx, 1));
            mx = fmaxf(mx, __shfl_xor_sync(0xffffffffu, mx, 2));
            const float m_new = fmaxf(m_i[r], mx);
            const float al    = __expf(m_i[r] - m_new);
            float sum = 0.f;
#pragma unroll
            for (int ni = 0; ni < 8; ni++) {
                const float p0 = __expf(s[ni][q0] - m_new);
                const float p1 = __expf(s[ni][q1] - m_new);
                s[ni][q0] = p0; s[ni][q1] = p1;
                sum += p0 + p1;
            }
            sum += __shfl_xor_sync(0xffffffffu, sum, 1);
            sum += __shfl_xor_sync(0xffffffffu, sum, 2);
            l_i[r] = l_i[r] * al + sum;
            m_i[r] = m_new;
            if (tig == 0) alp[srow + grp + 8 * r] = al;
        }

        // write P (tf32) to Ps[q][key], STS.64 conflict-free
#pragma unroll
        for (int ni = 0; ni < 8; ni++) {
#pragma unroll
            for (int r = 0; r < 2; r++) {
                uint2 pv = { f2tf32(s[ni][2 * r]), f2tf32(s[ni][2 * r + 1]) };
                *(uint2*)&Ps[(srow + grp + 8 * r) * ASTR + ni * 8 + tig * 2] = pv;
            }
        }
        __syncthreads();

        // ---- O phase: O^T += V^T P^T (32 d x 32 q per warp) ----
        // rescale accumulators by alpha of each q column
#pragma unroll
        for (int ni = 0; ni < 4; ni++) {
            float2 av = *(const float2*)&alp[qch + ni * 8 + tig * 2];
#pragma unroll
            for (int mi = 0; mi < 2; mi++) {
                o[mi][ni][0] *= av.x;
                o[mi][ni][1] *= av.y;
                o[mi][ni][2] *= av.x;
                o[mi][ni][3] *= av.y;
            }
        }
#pragma unroll
        for (int kk = 0; kk < 8; kk++) {
            unsigned a[2][4];
#pragma unroll
            for (int mi = 0; mi < 2; mi++) {
                const int ab = (kk * 8 + tig) * ASTR + dch + mi * 16 + grp;
                a[mi][0] = Vs[ab];
                a[mi][1] = Vs[ab + 8];
                a[mi][2] = Vs[ab + 4 * ASTR];
                a[mi][3] = Vs[ab + 4 * ASTR + 8];
            }
#pragma unroll
            for (int ni = 0; ni < 4; ni++) {
                const int bb = (qch + ni * 8 + grp) * ASTR + kk * 8 + tig;
                unsigned bf[2] = { Ps[bb], Ps[bb + 4] };
#pragma unroll
                for (int mi = 0; mi < 2; mi++)
                    mma_tf32(o[mi][ni], a[mi], bf);
            }
        }
    }

    __syncthreads();
    if (tig == 0) {
        alp[srow + grp]     = 1.f / l_i[0];
        alp[srow + grp + 8] = 1.f / l_i[1];
    }
    __syncthreads();

    // epilogue: O^T element (d, q) -> O[q][d] with 1/l scaling
    float* Ob = O + ((size_t)b * SEQ + qi * 128) * HID + h * HD;
#pragma unroll
    for (int mi = 0; mi < 2; mi++) {
        const int d0 = dch + mi * 16 + grp;
#pragma unroll
        for (int ni = 0; ni < 4; ni++) {
            const int q0 = qch + ni * 8 + tig * 2;
            const float i0 = alp[q0], i1 = alp[q0 + 1];
            Ob[(size_t)q0 * HID + d0]           = o[mi][ni][0] * i0;
            Ob[(size_t)(q0 + 1) * HID + d0]     = o[mi][ni][1] * i1;
            Ob[(size_t)q0 * HID + d0 + 8]       = o[mi][ni][2] * i0;
            Ob[(size_t)(q0 + 1) * HID + d0 + 8] = o[mi][ni][3] * i1;
        }
    }
}

// ---------------------------------------------------------------------------
extern "C" void kernel_launch(void* const* d_in, const int* in_sizes, int n_in,
                              void* d_out, int out_size)
{
    const float* query = (const float*)d_in[0];
    const float* key   = (const float*)d_in[1];
    const float* val   = (const float*)d_in[2];
    // d_in[3] = attn_mask (tril causal) — implemented directly in attn_tc
    const float* Wq = (const float*)d_in[4];
    const float* bq = (const float*)d_in[5];
    const float* Wk = (const float*)d_in[6];
    const float* bk = (const float*)d_in[7];
    const float* Wv = (const float*)d_in[8];
    const float* bv = (const float*)d_in[9];
    const float* Wo = (const float*)d_in[10];
    const float* bo = (const float*)d_in[11];
    float* out = (float*)d_out;

    void *pQ, *pK, *pV, *pAO;
    cudaGetSymbolAddress(&pQ,  g_Q);
    cudaGetSymbolAddress(&pK,  g_K);
    cudaGetSymbolAddress(&pV,  g_V);
    cudaGetSymbolAddress(&pAO, g_AO);

    cudaFuncSetAttribute(gemm_tf32,
                         cudaFuncAttributeMaxDynamicSharedMemorySize, GEMM_SMEM);
    cudaFuncSetAttribute(attn_tc,
                         cudaFuncAttributeMaxDynamicSharedMemorySize, ATT_SMEM);

    const dim3 ggrid(HID / 128, MTOT / 128);   // (8, 64)
    gemm_tf32<<<ggrid, 256, GEMM_SMEM>>>(query, Wq, bq, (float*)pQ);
    gemm_tf32<<<ggrid, 256, GEMM_SMEM>>>(key,   Wk, bk, (float*)pK);
    gemm_tf32<<<ggrid, 256, GEMM_SMEM>>>(val,   Wv, bv, (float*)pV);

    const dim3 agrid(SEQ / 128, NH, BATCH);     // (16, 16, 4)
    attn_tc<<<agrid, 256, ATT_SMEM>>>((const float*)pQ, (const float*)pK,
                                      (const float*)pV, (float*)pAO);

    gemm_tf32<<<ggrid, 256, GEMM_SMEM>>>((const float*)pAO, Wo, bo, out);
}

// round 4
// speedup vs baseline: 2.5892x; 1.2724x over previous
#include <cuda_runtime.h>
#include <math.h>

// Problem constants
#define BATCH 4
#define SEQ   2048
#define HID   1024
#define NH    16
#define HD    64
#define MTOT  (BATCH * SEQ)   // 8192

// Scratch (device globals: no runtime allocation allowed)
__device__ float g_Q [MTOT * HID];
__device__ float g_K [MTOT * HID];
__device__ float g_V [MTOT * HID];
__device__ float g_AO[MTOT * HID];

__device__ __forceinline__ unsigned f2tf32(float f) {
    unsigned u;
    asm volatile("cvt.rna.tf32.f32 %0, %1;" : "=r"(u) : "f"(f));
    return u;
}

__device__ __forceinline__ void mma_tf32(float* d, const unsigned* a, const unsigned* b) {
    asm volatile(
        "mma.sync.aligned.m16n8k8.row.col.f32.tf32.tf32.f32 "
        "{%0,%1,%2,%3}, {%4,%5,%6,%7}, {%8,%9}, {%0,%1,%2,%3};\n"
        : "+f"(d[0]), "+f"(d[1]), "+f"(d[2]), "+f"(d[3])
        : "r"(a[0]), "r"(a[1]), "r"(a[2]), "r"(a[3]),
          "r"(b[0]), "r"(b[1]));
}

__device__ __forceinline__ void cp_async16(void* dst, const void* src) {
    unsigned d = (unsigned)__cvta_generic_to_shared(dst);
    asm volatile("cp.async.cg.shared.global [%0], [%1], 16;\n" :: "r"(d), "l"(src));
}
__device__ __forceinline__ void cp_commit() {
    asm volatile("cp.async.commit_group;\n");
}
template <int N>
__device__ __forceinline__ void cp_wait() {
    asm volatile("cp.async.wait_group %0;\n" :: "n"(N));
}

// ---------------------------------------------------------------------------
// TF32 GEMM v3: C[M,1024] = A[M,1024] @ W[1024,1024]^T + bias
// 128x128x16 tile, 8 warps (2x4), 4-stage cp.async pipeline.
// Raw fp32 in smem (stride 20, conflict-free frags), cvt.rna post-LDS.
// ---------------------------------------------------------------------------
#define GK   1024
#define GN   1024
#define GSTR 20
#define GSTAGE (2 * 128 * GSTR)          // words per stage (A+B) = 5120
#define GEMM_SMEM (4 * GSTAGE * 4)       // 81920 bytes

__global__ __launch_bounds__(256, 2) void gemm_tf32(
    const float* __restrict__ A,
    const float* __restrict__ W,
    const float* __restrict__ bias,
    float* __restrict__ C)
{
    extern __shared__ float gsm[];

    const int tid  = threadIdx.x;
    const int lane = tid & 31;
    const int wid  = tid >> 5;
    const int wr   = wid >> 2;           // 0..1 : 64-row chunk
    const int wc   = wid & 3;            // 0..3 : 32-col chunk
    const int tig  = lane & 3;
    const int grp  = lane >> 2;

    const int row0 = blockIdx.y * 128;
    const int col0 = blockIdx.x * 128;

    float acc[4][4][4];
#pragma unroll
    for (int mi = 0; mi < 4; mi++)
#pragma unroll
        for (int ni = 0; ni < 4; ni++)
#pragma unroll
            for (int q = 0; q < 4; q++) acc[mi][ni][q] = 0.f;

    const int glr = tid >> 1;            // 0..127
    const int glk = (tid & 1) * 8;       // 0 or 8
    const float* Ap = A + (size_t)(row0 + glr) * GK + glk;
    const float* Wp = W + (size_t)(col0 + glr) * GK + glk;
    const int sdst = glr * GSTR + glk;

    // prologue: issue stages 0..2
#pragma unroll
    for (int s = 0; s < 3; s++) {
        float* As = gsm + s * GSTAGE;
        float* Bs = As + 128 * GSTR;
        cp_async16(&As[sdst],     Ap + s * 16);
        cp_async16(&As[sdst + 4], Ap + s * 16 + 4);
        cp_async16(&Bs[sdst],     Wp + s * 16);
        cp_async16(&Bs[sdst + 4], Wp + s * 16 + 4);
        cp_commit();
    }

    for (int it = 0; it < 64; it++) {
        if (it < 61) cp_wait<2>(); else cp_wait<0>();
        __syncthreads();

        const float* Ac = gsm + (it & 3) * GSTAGE;
        const float* Bc = Ac + 128 * GSTR;

        // issue stage it+3
        if (it + 3 < 64) {
            float* An = gsm + ((it + 3) & 3) * GSTAGE;
            float* Bn = An + 128 * GSTR;
            const int k0 = (it + 3) * 16;
            cp_async16(&An[sdst],     Ap + k0);
            cp_async16(&An[sdst + 4], Ap + k0 + 4);
            cp_async16(&Bn[sdst],     Wp + k0);
            cp_async16(&Bn[sdst + 4], Wp + k0 + 4);
            cp_commit();
        }

#pragma unroll
        for (int kk = 0; kk < 16; kk += 8) {
            unsigned af[4][4], bf[4][2];
#pragma unroll
            for (int mi = 0; mi < 4; mi++) {
                const int ab = (wr * 64 + mi * 16 + grp) * GSTR + kk + tig;
                af[mi][0] = f2tf32(Ac[ab]);
                af[mi][1] = f2tf32(Ac[ab + 8 * GSTR]);
                af[mi][2] = f2tf32(Ac[ab + 4]);
                af[mi][3] = f2tf32(Ac[ab + 8 * GSTR + 4]);
            }
#pragma unroll
            for (int ni = 0; ni < 4; ni++) {
                const int bb = (wc * 32 + ni * 8 + grp) * GSTR + kk + tig;
                bf[ni][0] = f2tf32(Bc[bb]);
                bf[ni][1] = f2tf32(Bc[bb + 4]);
            }
#pragma unroll
            for (int mi = 0; mi < 4; mi++)
#pragma unroll
                for (int ni = 0; ni < 4; ni++)
                    mma_tf32(acc[mi][ni], af[mi], bf[ni]);
        }
        __syncthreads();
    }

    // epilogue: bias add, float2 stores
#pragma unroll
    for (int mi = 0; mi < 4; mi++) {
        const int r = row0 + wr * 64 + mi * 16 + grp;
#pragma unroll
        for (int ni = 0; ni < 4; ni++) {
            const int c = col0 + wc * 32 + ni * 8 + tig * 2;
            const float b0 = bias[c], b1 = bias[c + 1];
            float2 v0, v1;
            v0.x = acc[mi][ni][0] + b0;
            v0.y = acc[mi][ni][1] + b1;
            v1.x = acc[mi][ni][2] + b0;
            v1.y = acc[mi][ni][3] + b1;
            *(float2*)(C + (size_t)r * GN + c)       = v0;
            *(float2*)(C + (size_t)(r + 8) * GN + c) = v1;
        }
    }
}

// ---------------------------------------------------------------------------
// TF32 tensor-core causal flash attention v2.
// BM=128, BN=64, 8 warps. Q fragments register-resident (loaded once).
// K/V tile kt+1 prefetched into registers during compute of tile kt.
// Single smem K/V buffer; Ps smem for the P round-trip; stride 72.
// ---------------------------------------------------------------------------
#define ASTR 72
#define KS_OFF 0                        // Ks[64][72]  (tf32 bits)
#define VS_OFF (64 * ASTR)              // Vs[64][72]
#define PS_OFF (128 * ASTR)             // Ps[128][72] (also Q staging)
#define AL_OFF (PS_OFF + 128 * ASTR)    // alpha / 1-over-l [128] floats
#define ATT_SMEM ((AL_OFF + 128) * 4)   // 74240 bytes

__global__ __launch_bounds__(256, 1) void attn_tc(
    const float* __restrict__ Q,
    const float* __restrict__ K,
    const float* __restrict__ V,
    float* __restrict__ O)
{
    extern __shared__ unsigned sm[];
    unsigned* Ks = sm + KS_OFF;
    unsigned* Vs = sm + VS_OFF;
    unsigned* Ps = sm + PS_OFF;
    float*    alp = (float*)(sm + AL_OFF);

    const int tid  = threadIdx.x;
    const int lane = tid & 31;
    const int wid  = tid >> 5;
    const int tig  = lane & 3;
    const int grp  = lane >> 2;

    const int qi = (gridDim.x - 1) - blockIdx.x;   // heavy blocks first
    const int h  = blockIdx.y;
    const int b  = blockIdx.z;

    const int srow = wid * 16;          // S-phase q rows for this warp
    const int dch  = (wid & 1) * 32;    // O-phase d chunk
    const int qch  = (wid >> 1) * 32;   // O-phase q chunk

    // ---- stage Q (raw fp32) through Ps region, extract register frags ----
    const float* Qb = Q + ((size_t)b * SEQ + qi * 128) * HID + h * HD;
    float* Qstage = (float*)Ps;
    for (int t = tid; t < 2048; t += 256) {
        const int r  = t >> 4;
        const int c4 = (t & 15) * 4;
        *(float4*)&Qstage[r * ASTR + c4] =
            *(const float4*)(Qb + (size_t)r * HID + c4);
    }
    __syncthreads();

    unsigned qf[8][4];
#pragma unroll
    for (int kk = 0; kk < 8; kk++) {
        const int ab = (srow + grp) * ASTR + kk * 8 + tig;
        qf[kk][0] = f2tf32(Qstage[ab]);
        qf[kk][1] = f2tf32(Qstage[ab + 8 * ASTR]);
        qf[kk][2] = f2tf32(Qstage[ab + 4]);
        qf[kk][3] = f2tf32(Qstage[ab + 8 * ASTR + 4]);
    }

    float m_i[2] = { -1e30f, -1e30f };
    float l_i[2] = { 0.f, 0.f };
    float o[2][4][4];
#pragma unroll
    for (int mi = 0; mi < 2; mi++)
#pragma unroll
        for (int ni = 0; ni < 4; ni++)
#pragma unroll
            for (int q = 0; q < 4; q++) o[mi][ni][q] = 0.f;

    const int ktmax = 2 * qi + 1;

    // ---- prefetch tile 0 into registers ----
    float4 kreg[4], vreg[4];
    {
        const float* Kb = K + ((size_t)b * SEQ) * HID + h * HD;
        const float* Vb = V + ((size_t)b * SEQ) * HID + h * HD;
#pragma unroll
        for (int t4 = 0; t4 < 4; t4++) {
            const int idx = tid + 256 * t4;
            const int r   = idx >> 4;
            const int c4  = (idx & 15) * 4;
            kreg[t4] = *(const float4*)(Kb + (size_t)r * HID + c4);
            vreg[t4] = *(const float4*)(Vb + (size_t)r * HID + c4);
        }
    }

    for (int kt = 0; kt <= ktmax; kt++) {
        __syncthreads();   // (a) everyone done reading Ks/Vs (and Q stage)

        // store prefetched tile (cvt to tf32)
#pragma unroll
        for (int t4 = 0; t4 < 4; t4++) {
            const int idx = tid + 256 * t4;
            const int r   = idx >> 4;
            const int c4  = (idx & 15) * 4;
            uint4 uk = { f2tf32(kreg[t4].x), f2tf32(kreg[t4].y),
                         f2tf32(kreg[t4].z), f2tf32(kreg[t4].w) };
            *(uint4*)&Ks[r * ASTR + c4] = uk;
            uint4 uv = { f2tf32(vreg[t4].x), f2tf32(vreg[t4].y),
                         f2tf32(vreg[t4].z), f2tf32(vreg[t4].w) };
            *(uint4*)&Vs[r * ASTR + c4] = uv;
        }
        __syncthreads();   // (b) tile visible

        // prefetch next tile (overlaps all compute below)
        if (kt < ktmax) {
            const float* Kb = K + ((size_t)b * SEQ + (kt + 1) * 64) * HID + h * HD;
            const float* Vb = V + ((size_t)b * SEQ + (kt + 1) * 64) * HID + h * HD;
#pragma unroll
            for (int t4 = 0; t4 < 4; t4++) {
                const int idx = tid + 256 * t4;
                const int r   = idx >> 4;
                const int c4  = (idx & 15) * 4;
                kreg[t4] = *(const float4*)(Kb + (size_t)r * HID + c4);
                vreg[t4] = *(const float4*)(Vb + (size_t)r * HID + c4);
            }
        }

        // ---- S phase: S = Q K^T (16 x 64 per warp) ----
        float s[8][4];
#pragma unroll
        for (int ni = 0; ni < 8; ni++)
#pragma unroll
            for (int q = 0; q < 4; q++) s[ni][q] = 0.f;

#pragma unroll
        for (int kk = 0; kk < 8; kk++) {
#pragma unroll
            for (int ni = 0; ni < 8; ni++) {
                const int bb = (ni * 8 + grp) * ASTR + kk * 8 + tig;
                unsigned bf[2] = { Ks[bb], Ks[bb + 4] };
                mma_tf32(s[ni], qf[kk], bf);
            }
        }

        // scale + causal mask
        const int row0 = qi * 128 + srow + grp;
        if (kt >= 2 * qi) {
#pragma unroll
            for (int ni = 0; ni < 8; ni++) {
                const int c0 = kt * 64 + ni * 8 + tig * 2;
#pragma unroll
                for (int q = 0; q < 4; q++) {
                    const int row = (q < 2) ? row0 : row0 + 8;
                    const int col = c0 + (q & 1);
                    s[ni][q] = (col > row) ? -1e30f : s[ni][q] * 0.125f;
                }
            }
        } else {
#pragma unroll
            for (int ni = 0; ni < 8; ni++)
#pragma unroll
                for (int q = 0; q < 4; q++) s[ni][q] *= 0.125f;
        }

        // online softmax (2 rows per thread; quad shfl reduction)
#pragma unroll
        for (int r = 0; r < 2; r++) {
            const int q0 = 2 * r, q1 = 2 * r + 1;
            float mx = -1e30f;
#pragma unroll
            for (int ni = 0; ni < 8; ni++)
                mx = fmaxf(mx, fmaxf(s[ni][q0], s[ni][q1]));
            mx = fmaxf(mx, __shfl_xor_sync(0xffffffffu, mx, 1));
            mx = fmaxf(mx, __shfl_xor_sync(0xffffffffu, mx, 2));
            const float m_new = fmaxf(m_i[r], mx);
            const float al    = __expf(m_i[r] - m_new);
            float sum = 0.f;
#pragma unroll
            for (int ni = 0; ni < 8; ni++) {
                const float p0 = __expf(s[ni][q0] - m_new);
                const float p1 = __expf(s[ni][q1] - m_new);
                s[ni][q0] = p0; s[ni][q1] = p1;
                sum += p0 + p1;
            }
            sum += __shfl_xor_sync(0xffffffffu, sum, 1);
            sum += __shfl_xor_sync(0xffffffffu, sum, 2);
            l_i[r] = l_i[r] * al + sum;
            m_i[r] = m_new;
            if (tig == 0) alp[srow + grp + 8 * r] = al;
        }

        // write P (tf32) to Ps[q][key]
#pragma unroll
        for (int ni = 0; ni < 8; ni++) {
#pragma unroll
            for (int r = 0; r < 2; r++) {
                uint2 pv = { f2tf32(s[ni][2 * r]), f2tf32(s[ni][2 * r + 1]) };
                *(uint2*)&Ps[(srow + grp + 8 * r) * ASTR + ni * 8 + tig * 2] = pv;
            }
        }
        __syncthreads();   // (c) Ps + alp visible

        // ---- O phase: O^T += V^T P^T (32 d x 32 q per warp) ----
#pragma unroll
        for (int ni = 0; ni < 4; ni++) {
            float2 av = *(const float2*)&alp[qch + ni * 8 + tig * 2];
#pragma unroll
            for (int mi = 0; mi < 2; mi++) {
                o[mi][ni][0] *= av.x;
                o[mi][ni][1] *= av.y;
                o[mi][ni][2] *= av.x;
                o[mi][ni][3] *= av.y;
            }
        }
#pragma unroll
        for (int kk = 0; kk < 8; kk++) {
            unsigned a[2][4];
#pragma unroll
            for (int mi = 0; mi < 2; mi++) {
                const int ab = (kk * 8 + tig) * ASTR + dch + mi * 16 + grp;
                a[mi][0] = Vs[ab];
                a[mi][1] = Vs[ab + 8];
                a[mi][2] = Vs[ab + 4 * ASTR];
                a[mi][3] = Vs[ab + 4 * ASTR + 8];
            }
#pragma unroll
            for (int ni = 0; ni < 4; ni++) {
                const int bb = (qch + ni * 8 + grp) * ASTR + kk * 8 + tig;
                unsigned bf[2] = { Ps[bb], Ps[bb + 4] };
#pragma unroll
                for (int mi = 0; mi < 2; mi++)
                    mma_tf32(o[mi][ni], a[mi], bf);
            }
        }
    }

    __syncthreads();
    if (tig == 0) {
        alp[srow + grp]     = 1.f / l_i[0];
        alp[srow + grp + 8] = 1.f / l_i[1];
    }
    __syncthreads();

    // epilogue: O^T element (d, q) -> O[q][d] with 1/l scaling
    float* Ob = O + ((size_t)b * SEQ + qi * 128) * HID + h * HD;
#pragma unroll
    for (int mi = 0; mi < 2; mi++) {
        const int d0 = dch + mi * 16 + grp;
#pragma unroll
        for (int ni = 0; ni < 4; ni++) {
            const int q0 = qch + ni * 8 + tig * 2;
            const float i0 = alp[q0], i1 = alp[q0 + 1];
            Ob[(size_t)q0 * HID + d0]           = o[mi][ni][0] * i0;
            Ob[(size_t)(q0 + 1) * HID + d0]     = o[mi][ni][1] * i1;
            Ob[(size_t)q0 * HID + d0 + 8]       = o[mi][ni][2] * i0;
            Ob[(size_t)(q0 + 1) * HID + d0 + 8] = o[mi][ni][3] * i1;
        }
    }
}

// ---------------------------------------------------------------------------
extern "C" void kernel_launch(void* const* d_in, const int* in_sizes, int n_in,
                              void* d_out, int out_size)
{
    const float* query = (const float*)d_in[0];
    const float* key   = (const float*)d_in[1];
    const float* val   = (const float*)d_in[2];
    // d_in[3] = attn_mask (tril causal) — implemented directly in attn_tc
    const float* Wq = (const float*)d_in[4];
    const float* bq = (const float*)d_in[5];
    const float* Wk = (const float*)d_in[6];
    const float* bk = (const float*)d_in[7];
    const float* Wv = (const float*)d_in[8];
    const float* bv = (const float*)d_in[9];
    const float* Wo = (const float*)d_in[10];
    const float* bo = (const float*)d_in[11];
    float* out = (float*)d_out;

    void *pQ, *pK, *pV, *pAO;
    cudaGetSymbolAddress(&pQ,  g_Q);
    cudaGetSymbolAddress(&pK,  g_K);
    cudaGetSymbolAddress(&pV,  g_V);
    cudaGetSymbolAddress(&pAO, g_AO);

    cudaFuncSetAttribute(gemm_tf32,
                         cudaFuncAttributeMaxDynamicSharedMemorySize, GEMM_SMEM);
    cudaFuncSetAttribute(attn_tc,
                         cudaFuncAttributeMaxDynamicSharedMemorySize, ATT_SMEM);

    const dim3 ggrid(HID / 128, MTOT / 128);   // (8, 64)
    gemm_tf32<<<ggrid, 256, GEMM_SMEM>>>(query, Wq, bq, (float*)pQ);
    gemm_tf32<<<ggrid, 256, GEMM_SMEM>>>(key,   Wk, bk, (float*)pK);
    gemm_tf32<<<ggrid, 256, GEMM_SMEM>>>(val,   Wv, bv, (float*)pV);

    const dim3 agrid(SEQ / 128, NH, BATCH);     // (16, 16, 4)
    attn_tc<<<agrid, 256, ATT_SMEM>>>((const float*)pQ, (const float*)pK,
                                      (const float*)pV, (float*)pAO);

    gemm_tf32<<<ggrid, 256, GEMM_SMEM>>>((const float*)pAO, Wo, bo, out);
}

// round 6
// speedup vs baseline: 2.6598x; 1.0273x over previous
#include <cuda_runtime.h>
#include <math.h>

// Problem constants
#define BATCH 4
#define SEQ   2048
#define HID   1024
#define NH    16
#define HD    64
#define MTOT  (BATCH * SEQ)   // 8192

// Scratch (device globals: no runtime allocation allowed)
__device__ float g_Q [MTOT * HID];
__device__ float g_K [MTOT * HID];
__device__ float g_V [MTOT * HID];
__device__ float g_AO[MTOT * HID];
// pre-rounded (tf32/RNA) copies of inputs
__device__ float g_Xq[MTOT * HID];
__device__ float g_Xk[MTOT * HID];
__device__ float g_Xv[MTOT * HID];
__device__ float g_Wq[HID * HID];
__device__ float g_Wk[HID * HID];
__device__ float g_Wv[HID * HID];
__device__ float g_Wo[HID * HID];

__device__ __forceinline__ unsigned f2tf32(float f) {
    unsigned u;
    asm volatile("cvt.rna.tf32.f32 %0, %1;" : "=r"(u) : "f"(f));
    return u;
}

__device__ __forceinline__ void mma_tf32(float* d, const unsigned* a, const unsigned* b) {
    asm volatile(
        "mma.sync.aligned.m16n8k8.row.col.f32.tf32.tf32.f32 "
        "{%0,%1,%2,%3}, {%4,%5,%6,%7}, {%8,%9}, {%0,%1,%2,%3};\n"
        : "+f"(d[0]), "+f"(d[1]), "+f"(d[2]), "+f"(d[3])
        : "r"(a[0]), "r"(a[1]), "r"(a[2]), "r"(a[3]),
          "r"(b[0]), "r"(b[1]));
}

__device__ __forceinline__ void cp_async16(void* dst, const void* src) {
    unsigned d = (unsigned)__cvta_generic_to_shared(dst);
    asm volatile("cp.async.cg.shared.global [%0], [%1], 16;\n" :: "r"(d), "l"(src));
}
__device__ __forceinline__ void cp_commit() {
    asm volatile("cp.async.commit_group;\n");
}
template <int N>
__device__ __forceinline__ void cp_wait() {
    asm volatile("cp.async.wait_group %0;\n" :: "n"(N));
}

// ---------------------------------------------------------------------------
// Pre-pass: round fp32 -> tf32 (RNA), store as fp32 bit pattern.
// ---------------------------------------------------------------------------
__global__ __launch_bounds__(256) void cvt_rna_kernel(
    const float* __restrict__ src, float* __restrict__ dst, int n4)
{
    const int i = blockIdx.x * blockDim.x + threadIdx.x;
    if (i < n4) {
        float4 v = ((const float4*)src)[i];
        uint4 u = { f2tf32(v.x), f2tf32(v.y), f2tf32(v.z), f2tf32(v.w) };
        ((uint4*)dst)[i] = u;
    }
}

// ---------------------------------------------------------------------------
// TF32 GEMM v4: C[M,1024] = A[M,1024] @ W[1024,1024]^T + bias
// A and W PRE-ROUNDED to tf32 -> no cvt in inner loop.
// 128x128x16 tile, 8 warps (2x4), 4-stage cp.async pipeline, stride 20.
// ROUND_OUT: round the result to tf32 before storing (for Q/K/V).
// ---------------------------------------------------------------------------
#define GK   1024
#define GN   1024
#define GSTR 20
#define GSTAGE (2 * 128 * GSTR)          // words per stage (A+B) = 5120
#define GEMM_SMEM (4 * GSTAGE * 4)       // 81920 bytes

template <bool ROUND_OUT>
__global__ __launch_bounds__(256, 2) void gemm_tf32(
    const float* __restrict__ A,
    const float* __restrict__ W,
    const float* __restrict__ bias,
    float* __restrict__ C)
{
    extern __shared__ float gsm[];

    const int tid  = threadIdx.x;
    const int lane = tid & 31;
    const int wid  = tid >> 5;
    const int wr   = wid >> 2;
    const int wc   = wid & 3;
    const int tig  = lane & 3;
    const int grp  = lane >> 2;

    const int row0 = blockIdx.y * 128;
    const int col0 = blockIdx.x * 128;

    float acc[4][4][4];
#pragma unroll
    for (int mi = 0; mi < 4; mi++)
#pragma unroll
        for (int ni = 0; ni < 4; ni++)
#pragma unroll
            for (int q = 0; q < 4; q++) acc[mi][ni][q] = 0.f;

    const int glr = tid >> 1;
    const int glk = (tid & 1) * 8;
    const float* Ap = A + (size_t)(row0 + glr) * GK + glk;
    const float* Wp = W + (size_t)(col0 + glr) * GK + glk;
    const int sdst = glr * GSTR + glk;

#pragma unroll
    for (int s = 0; s < 3; s++) {
        float* As = gsm + s * GSTAGE;
        float* Bs = As + 128 * GSTR;
        cp_async16(&As[sdst],     Ap + s * 16);
        cp_async16(&As[sdst + 4], Ap + s * 16 + 4);
        cp_async16(&Bs[sdst],     Wp + s * 16);
        cp_async16(&Bs[sdst + 4], Wp + s * 16 + 4);
        cp_commit();
    }

    for (int it = 0; it < 64; it++) {
        if (it < 61) cp_wait<2>(); else cp_wait<0>();
        __syncthreads();

        const unsigned* Ac = (const unsigned*)(gsm + (it & 3) * GSTAGE);
        const unsigned* Bc = Ac + 128 * GSTR;

        if (it + 3 < 64) {
            float* An = gsm + ((it + 3) & 3) * GSTAGE;
            float* Bn = An + 128 * GSTR;
            const int k0 = (it + 3) * 16;
            cp_async16(&An[sdst],     Ap + k0);
            cp_async16(&An[sdst + 4], Ap + k0 + 4);
            cp_async16(&Bn[sdst],     Wp + k0);
            cp_async16(&Bn[sdst + 4], Wp + k0 + 4);
            cp_commit();
        }

#pragma unroll
        for (int kk = 0; kk < 16; kk += 8) {
            unsigned af[4][4], bf[4][2];
#pragma unroll
            for (int mi = 0; mi < 4; mi++) {
                const int ab = (wr * 64 + mi * 16 + grp) * GSTR + kk + tig;
                af[mi][0] = Ac[ab];
                af[mi][1] = Ac[ab + 8 * GSTR];
                af[mi][2] = Ac[ab + 4];
                af[mi][3] = Ac[ab + 8 * GSTR + 4];
            }
#pragma unroll
            for (int ni = 0; ni < 4; ni++) {
                const int bb = (wc * 32 + ni * 8 + grp) * GSTR + kk + tig;
                bf[ni][0] = Bc[bb];
                bf[ni][1] = Bc[bb + 4];
            }
#pragma unroll
            for (int mi = 0; mi < 4; mi++)
#pragma unroll
                for (int ni = 0; ni < 4; ni++)
                    mma_tf32(acc[mi][ni], af[mi], bf[ni]);
        }
        __syncthreads();
    }

#pragma unroll
    for (int mi = 0; mi < 4; mi++) {
        const int r = row0 + wr * 64 + mi * 16 + grp;
#pragma unroll
        for (int ni = 0; ni < 4; ni++) {
            const int c = col0 + wc * 32 + ni * 8 + tig * 2;
            const float b0 = bias[c], b1 = bias[c + 1];
            float v0 = acc[mi][ni][0] + b0;
            float v1 = acc[mi][ni][1] + b1;
            float v2 = acc[mi][ni][2] + b0;
            float v3 = acc[mi][ni][3] + b1;
            if (ROUND_OUT) {
                v0 = __uint_as_float(f2tf32(v0));
                v1 = __uint_as_float(f2tf32(v1));
                v2 = __uint_as_float(f2tf32(v2));
                v3 = __uint_as_float(f2tf32(v3));
            }
            float2 w0 = { v0, v1 }, w1 = { v2, v3 };
            *(float2*)(C + (size_t)r * GN + c)       = w0;
            *(float2*)(C + (size_t)(r + 8) * GN + c) = w1;
        }
    }
}

// ---------------------------------------------------------------------------
// TF32 causal flash attention v3.
// Q/K/V pre-rounded -> no cvt except P. Q frags register-resident.
// K/V: 2-stage cp.async pipeline. __launch_bounds__(256,2) -> 2 CTAs/SM.
// ---------------------------------------------------------------------------
#define ASTR 72
#define KVSTG (2 * 64 * ASTR)            // words per stage (K+V) = 9216
#define PS_OFF (2 * KVSTG)               // Ps[128][72] (also Q staging)
#define AL_OFF (PS_OFF + 128 * ASTR)
#define ATT_SMEM ((AL_OFF + 128) * 4)    // 111104 bytes

__global__ __launch_bounds__(256, 2) void attn_tc(
    const float* __restrict__ Q,
    const float* __restrict__ K,
    const float* __restrict__ V,
    float* __restrict__ O)
{
    extern __shared__ unsigned sm[];
    unsigned* Ps = sm + PS_OFF;
    float*    alp = (float*)(sm + AL_OFF);

    const int tid  = threadIdx.x;
    const int lane = tid & 31;
    const int wid  = tid >> 5;
    const int tig  = lane & 3;
    const int grp  = lane >> 4 ? (lane >> 2) : (lane >> 2);   // lane>>2
    const int grp2 = lane >> 2;

    const int qi = (gridDim.x - 1) - blockIdx.x;   // heavy blocks first
    const int h  = blockIdx.y;
    const int b  = blockIdx.z;

    const int srow = wid * 16;          // S-phase q rows for this warp
    const int dch  = (wid & 1) * 32;    // O-phase d chunk
    const int qch  = (wid >> 1) * 32;   // O-phase q chunk

    const int ktmax = 2 * qi + 1;       // >= 1 always

    // per-thread gmem->smem copy coords for 64x64 tiles
    const int cr  = tid >> 4;           // row 0..15 (+16 per chunk)
    const int cc4 = (tid & 15) * 4;     // col

    const float* Kbase = K + (size_t)b * SEQ * HID + h * HD;
    const float* Vbase = V + (size_t)b * SEQ * HID + h * HD;

    // prologue: stage Q (pre-rounded fp32 bits) through Ps, grab frags
    const float* Qb = Q + ((size_t)b * SEQ + qi * 128) * HID + h * HD;
    for (int t = tid; t < 2048; t += 256) {
        const int r  = t >> 4;
        const int c4 = (t & 15) * 4;
        *(float4*)&((float*)Ps)[r * ASTR + c4] =
            *(const float4*)(Qb + (size_t)r * HID + c4);
    }

    // issue K/V stages 0 and 1 while Q settles
    {
        const float* Kb = Kbase;
        const float* Vb = Vbase;
        unsigned* Kd = sm;              // stage 0
        unsigned* Vd = Kd + 64 * ASTR;
#pragma unroll
        for (int t4 = 0; t4 < 4; t4++) {
            const int r = cr + t4 * 16;
            cp_async16(&Kd[r * ASTR + cc4], Kb + (size_t)r * HID + cc4);
            cp_async16(&Vd[r * ASTR + cc4], Vb + (size_t)r * HID + cc4);
        }
        cp_commit();
        Kb = Kbase + (size_t)64 * HID;
        Vb = Vbase + (size_t)64 * HID;
        Kd = sm + KVSTG;                // stage 1
        Vd = Kd + 64 * ASTR;
#pragma unroll
        for (int t4 = 0; t4 < 4; t4++) {
            const int r = cr + t4 * 16;
            cp_async16(&Kd[r * ASTR + cc4], Kb + (size_t)r * HID + cc4);
            cp_async16(&Vd[r * ASTR + cc4], Vb + (size_t)r * HID + cc4);
        }
        cp_commit();
    }

    __syncthreads();    // Q staged

    unsigned qf[8][4];
#pragma unroll
    for (int kk = 0; kk < 8; kk++) {
        const int ab = (srow + grp2) * ASTR + kk * 8 + tig;
        qf[kk][0] = Ps[ab];
        qf[kk][1] = Ps[ab + 8 * ASTR];
        qf[kk][2] = Ps[ab + 4];
        qf[kk][3] = Ps[ab + 8 * ASTR + 4];
    }

    float m_i[2] = { -1e30f, -1e30f };
    float l_i[2] = { 0.f, 0.f };
    float o[2][4][4];
#pragma unroll
    for (int mi = 0; mi < 2; mi++)
#pragma unroll
        for (int ni = 0; ni < 4; ni++)
#pragma unroll
            for (int q = 0; q < 4; q++) o[mi][ni][q] = 0.f;

    for (int kt = 0; kt <= ktmax; kt++) {
        if (kt < ktmax) cp_wait<1>(); else cp_wait<0>();
        __syncthreads();   // stage (kt&1) ready for everyone; Ps free

        const unsigned* Ks = sm + (kt & 1) * KVSTG;
        const unsigned* Vs = Ks + 64 * ASTR;

        // ---- S phase: S = Q K^T (16 x 64 per warp) ----
        float s[8][4];
#pragma unroll
        for (int ni = 0; ni < 8; ni++)
#pragma unroll
            for (int q = 0; q < 4; q++) s[ni][q] = 0.f;

#pragma unroll
        for (int kk = 0; kk < 8; kk++) {
#pragma unroll
            for (int ni = 0; ni < 8; ni++) {
                const int bb = (ni * 8 + grp2) * ASTR + kk * 8 + tig;
                unsigned bf[2] = { Ks[bb], Ks[bb + 4] };
                mma_tf32(s[ni], qf[kk], bf);
            }
        }

        // scale + causal mask
        const int row0 = qi * 128 + srow + grp2;
        if (kt >= 2 * qi) {
#pragma unroll
            for (int ni = 0; ni < 8; ni++) {
                const int c0 = kt * 64 + ni * 8 + tig * 2;
#pragma unroll
                for (int q = 0; q < 4; q++) {
                    const int row = (q < 2) ? row0 : row0 + 8;
                    const int col = c0 + (q & 1);
                    s[ni][q] = (col > row) ? -1e30f : s[ni][q] * 0.125f;
                }
            }
        } else {
#pragma unroll
            for (int ni = 0; ni < 8; ni++)
#pragma unroll
                for (int q = 0; q < 4; q++) s[ni][q] *= 0.125f;
        }

        // online softmax
#pragma unroll
        for (int r = 0; r < 2; r++) {
            const int q0 = 2 * r, q1 = 2 * r + 1;
            float mx = -1e30f;
#pragma unroll
            for (int ni = 0; ni < 8; ni++)
                mx = fmaxf(mx, fmaxf(s[ni][q0], s[ni][q1]));
            mx = fmaxf(mx, __shfl_xor_sync(0xffffffffu, mx, 1));
            mx = fmaxf(mx, __shfl_xor_sync(0xffffffffu, mx, 2));
            const float m_new = fmaxf(m_i[r], mx);
            const float al    = __expf(m_i[r] - m_new);
            float sum = 0.f;
#pragma unroll
            for (int ni = 0; ni < 8; ni++) {
                const float p0 = __expf(s[ni][q0] - m_new);
                const float p1 = __expf(s[ni][q1] - m_new);
                s[ni][q0] = p0; s[ni][q1] = p1;
                sum += p0 + p1;
            }
            sum += __shfl_xor_sync(0xffffffffu, sum, 1);
            sum += __shfl_xor_sync(0xffffffffu, sum, 2);
            l_i[r] = l_i[r] * al + sum;
            m_i[r] = m_new;
            if (tig == 0) alp[srow + grp2 + 8 * r] = al;
        }

        // write P (tf32) to Ps[q][key]
#pragma unroll
        for (int ni = 0; ni < 8; ni++) {
#pragma unroll
            for (int r = 0; r < 2; r++) {
                uint2 pv = { f2tf32(s[ni][2 * r]), f2tf32(s[ni][2 * r + 1]) };
                *(uint2*)&Ps[(srow + grp2 + 8 * r) * ASTR + ni * 8 + tig * 2] = pv;
            }
        }
        __syncthreads();   // Ps + alp visible

        // ---- O phase: O^T += V^T P^T (32 d x 32 q per warp) ----
#pragma unroll
        for (int ni = 0; ni < 4; ni++) {
            float2 av = *(const float2*)&alp[qch + ni * 8 + tig * 2];
#pragma unroll
            for (int mi = 0; mi < 2; mi++) {
                o[mi][ni][0] *= av.x;
                o[mi][ni][1] *= av.y;
                o[mi][ni][2] *= av.x;
                o[mi][ni][3] *= av.y;
            }
        }
#pragma unroll
        for (int kk = 0; kk < 8; kk++) {
            unsigned a[2][4];
#pragma unroll
            for (int mi = 0; mi < 2; mi++) {
                const int ab = (kk * 8 + tig) * ASTR + dch + mi * 16 + grp2;
                a[mi][0] = Vs[ab];
                a[mi][1] = Vs[ab + 8];
                a[mi][2] = Vs[ab + 4 * ASTR];
                a[mi][3] = Vs[ab + 4 * ASTR + 8];
            }
#pragma unroll
            for (int ni = 0; ni < 4; ni++) {
                const int bb = (qch + ni * 8 + grp2) * ASTR + kk * 8 + tig;
                unsigned bf[2] = { Ps[bb], Ps[bb + 4] };
#pragma unroll
                for (int mi = 0; mi < 2; mi++)
                    mma_tf32(o[mi][ni], a[mi], bf);
            }
        }
        __syncthreads();   // all warps done reading stage (kt&1)

        // issue stage kt+2 into the buffer just freed
        if (kt + 2 <= ktmax) {
            const float* Kb = Kbase + (size_t)(kt + 2) * 64 * HID;
            const float* Vb = Vbase + (size_t)(kt + 2) * 64 * HID;
            unsigned* Kd = sm + ((kt + 2) & 1) * KVSTG;
            unsigned* Vd = Kd + 64 * ASTR;
#pragma unroll
            for (int t4 = 0; t4 < 4; t4++) {
                const int r = cr + t4 * 16;
                cp_async16(&Kd[r * ASTR + cc4], Kb + (size_t)r * HID + cc4);
                cp_async16(&Vd[r * ASTR + cc4], Vb + (size_t)r * HID + cc4);
            }
            cp_commit();
        }
    }

    __syncthreads();
    if (tig == 0) {
        alp[srow + grp2]     = 1.f / l_i[0];
        alp[srow + grp2 + 8] = 1.f / l_i[1];
    }
    __syncthreads();

    // epilogue: O^T element (d, q) -> O[q][d], tf32-rounded for the Wo GEMM
    float* Ob = O + ((size_t)b * SEQ + qi * 128) * HID + h * HD;
#pragma unroll
    for (int mi = 0; mi < 2; mi++) {
        const int d0 = dch + mi * 16 + grp2;
#pragma unroll
        for (int ni = 0; ni < 4; ni++) {
            const int q0 = qch + ni * 8 + tig * 2;
            const float i0 = alp[q0], i1 = alp[q0 + 1];
            Ob[(size_t)q0 * HID + d0]           = __uint_as_float(f2tf32(o[mi][ni][0] * i0));
            Ob[(size_t)(q0 + 1) * HID + d0]     = __uint_as_float(f2tf32(o[mi][ni][1] * i1));
            Ob[(size_t)q0 * HID + d0 + 8]       = __uint_as_float(f2tf32(o[mi][ni][2] * i0));
            Ob[(size_t)(q0 + 1) * HID + d0 + 8] = __uint_as_float(f2tf32(o[mi][ni][3] * i1));
        }
    }
}

// ---------------------------------------------------------------------------
extern "C" void kernel_launch(void* const* d_in, const int* in_sizes, int n_in,
                              void* d_out, int out_size)
{
    const float* query = (const float*)d_in[0];
    const float* key   = (const float*)d_in[1];
    const float* val   = (const float*)d_in[2];
    // d_in[3] = attn_mask (tril causal) — implemented directly in attn_tc
    const float* Wq = (const float*)d_in[4];
    const float* bq = (const float*)d_in[5];
    const float* Wk = (const float*)d_in[6];
    const float* bk = (const float*)d_in[7];
    const float* Wv = (const float*)d_in[8];
    const float* bv = (const float*)d_in[9];
    const float* Wo = (const float*)d_in[10];
    const float* bo = (const float*)d_in[11];
    float* out = (float*)d_out;

    void *pQ, *pK, *pV, *pAO, *pXq, *pXk, *pXv, *pWq, *pWk, *pWv, *pWo;
    cudaGetSymbolAddress(&pQ,  g_Q);
    cudaGetSymbolAddress(&pK,  g_K);
    cudaGetSymbolAddress(&pV,  g_V);
    cudaGetSymbolAddress(&pAO, g_AO);
    cudaGetSymbolAddress(&pXq, g_Xq);
    cudaGetSymbolAddress(&pXk, g_Xk);
    cudaGetSymbolAddress(&pXv, g_Xv);
    cudaGetSymbolAddress(&pWq, g_Wq);
    cudaGetSymbolAddress(&pWk, g_Wk);
    cudaGetSymbolAddress(&pWv, g_Wv);
    cudaGetSymbolAddress(&pWo, g_Wo);

    cudaFuncSetAttribute(gemm_tf32<true>,
                         cudaFuncAttributeMaxDynamicSharedMemorySize, GEMM_SMEM);
    cudaFuncSetAttribute(gemm_tf32<false>,
                         cudaFuncAttributeMaxDynamicSharedMemorySize, GEMM_SMEM);
    cudaFuncSetAttribute(attn_tc,
                         cudaFuncAttributeMaxDynamicSharedMemorySize, ATT_SMEM);

    // pre-pass: round inputs to tf32
    const int nX4 = MTOT * HID / 4;   // 2.1M
    const int nW4 = HID * HID / 4;    // 262144
    cvt_rna_kernel<<<(nX4 + 255) / 256, 256>>>(query, (float*)pXq, nX4);
    cvt_rna_kernel<<<(nX4 + 255) / 256, 256>>>(key,   (float*)pXk, nX4);
    cvt_rna_kernel<<<(nX4 + 255) / 256, 256>>>(val,   (float*)pXv, nX4);
    cvt_rna_kernel<<<(nW4 + 255) / 256, 256>>>(Wq, (float*)pWq, nW4);
    cvt_rna_kernel<<<(nW4 + 255) / 256, 256>>>(Wk, (float*)pWk, nW4);
    cvt_rna_kernel<<<(nW4 + 255) / 256, 256>>>(Wv, (float*)pWv, nW4);
    cvt_rna_kernel<<<(nW4 + 255) / 256, 256>>>(Wo, (float*)pWo, nW4);

    const dim3 ggrid(HID / 128, MTOT / 128);   // (8, 64)
    gemm_tf32<true><<<ggrid, 256, GEMM_SMEM>>>((const float*)pXq, (const float*)pWq, bq, (float*)pQ);
    gemm_tf32<true><<<ggrid, 256, GEMM_SMEM>>>((const float*)pXk, (const float*)pWk, bk, (float*)pK);
    gemm_tf32<true><<<ggrid, 256, GEMM_SMEM>>>((const float*)pXv, (const float*)pWv, bv, (float*)pV);

    const dim3 agrid(SEQ / 128, NH, BATCH);     // (16, 16, 4)
    attn_tc<<<agrid, 256, ATT_SMEM>>>((const float*)pQ, (const float*)pK,
                                      (const float*)pV, (float*)pAO);

    gemm_tf32<false><<<ggrid, 256, GEMM_SMEM>>>((const float*)pAO, (const float*)pWo, bo, out);
}

// round 9
// speedup vs baseline: 5.7830x; 2.1742x over previous
#include <cuda_runtime.h>
#include <cuda_fp16.h>
#include <math.h>
#include <stdint.h>

// Problem constants
#define BATCH 4
#define SEQ   2048
#define HID   1024
#define NH    16
#define HD    64
#define MTOT  (BATCH * SEQ)   // 8192
#define GK    1024
#define GN    1024

// Scratch (device globals: no runtime allocation allowed)
__device__ __half g_Q [MTOT * HID];
__device__ __half g_K [MTOT * HID];
__device__ __half g_V [MTOT * HID];
__device__ __half g_AO[MTOT * HID];
// fp16 copies of inputs
__device__ __half g_Xq[MTOT * HID];
__device__ __half g_Xk[MTOT * HID];
__device__ __half g_Xv[MTOT * HID];
__device__ __half g_Wq[HID * HID];
__device__ __half g_Wk[HID * HID];
__device__ __half g_Wv[HID * HID];
__device__ __half g_Wo[HID * HID];

__device__ __forceinline__ void mma_f16(float* d, const unsigned* a, const unsigned* b) {
    asm volatile(
        "mma.sync.aligned.m16n8k16.row.col.f32.f16.f16.f32 "
        "{%0,%1,%2,%3}, {%4,%5,%6,%7}, {%8,%9}, {%0,%1,%2,%3};\n"
        : "+f"(d[0]), "+f"(d[1]), "+f"(d[2]), "+f"(d[3])
        : "r"(a[0]), "r"(a[1]), "r"(a[2]), "r"(a[3]),
          "r"(b[0]), "r"(b[1]));
}

__device__ __forceinline__ void cp_async16(void* dst, const void* src) {
    unsigned d = (unsigned)__cvta_generic_to_shared(dst);
    asm volatile("cp.async.cg.shared.global [%0], [%1], 16;\n" :: "r"(d), "l"(src));
}
__device__ __forceinline__ void cp_commit() {
    asm volatile("cp.async.commit_group;\n");
}
template <int N>
__device__ __forceinline__ void cp_wait() {
    asm volatile("cp.async.wait_group %0;\n" :: "n"(N));
}

#define LDSM_X4(R0, R1, R2, R3, ADDR) \
    asm volatile("ldmatrix.sync.aligned.m8n8.x4.shared.b16 {%0,%1,%2,%3}, [%4];" \
        : "=r"(R0), "=r"(R1), "=r"(R2), "=r"(R3) : "r"(ADDR))
#define LDSM_X4T(R0, R1, R2, R3, ADDR) \
    asm volatile("ldmatrix.sync.aligned.m8n8.x4.trans.shared.b16 {%0,%1,%2,%3}, [%4];" \
        : "=r"(R0), "=r"(R1), "=r"(R2), "=r"(R3) : "r"(ADDR))

__device__ __forceinline__ unsigned packh2(float lo, float hi) {
    __half2 h = __floats2half2_rn(lo, hi);
    return *reinterpret_cast<unsigned*>(&h);
}

// ---------------------------------------------------------------------------
// Pre-pass: fp32 -> fp16 (RN).
// ---------------------------------------------------------------------------
__global__ __launch_bounds__(256) void cvt_h_kernel(
    const float* __restrict__ src, __half* __restrict__ dst, int n8)
{
    const int i = blockIdx.x * blockDim.x + threadIdx.x;
    if (i < n8) {
        float4 v0 = ((const float4*)src)[2 * i];
        float4 v1 = ((const float4*)src)[2 * i + 1];
        unsigned u[4];
        u[0] = packh2(v0.x, v0.y);
        u[1] = packh2(v0.z, v0.w);
        u[2] = packh2(v1.x, v1.y);
        u[3] = packh2(v1.z, v1.w);
        ((uint4*)dst)[i] = *(uint4*)u;
    }
}

// ---------------------------------------------------------------------------
// FP16 GEMM: C[M,1024] = A[M,1024] @ W[1024,1024]^T + bias
// 128x128 tile, BK=32 halves, 8 warps (2x4), 4-stage cp.async pipeline.
// Smem row stride 40 halves -> conflict-free scalar frag loads.
// OUT_FLOAT: store fp32 (final GEMM); else fp16 (Q/K/V).
// ---------------------------------------------------------------------------
#define GSTR   40                          // halves per smem row
#define GSTG_H (2 * 128 * GSTR)            // halves per stage (A+B) = 10240
#define GEMM_SMEM (4 * GSTG_H * 2)         // 81920 bytes

template <bool OUT_FLOAT>
__global__ __launch_bounds__(256, 2) void gemm_f16(
    const __half* __restrict__ A,
    const __half* __restrict__ W,
    const float* __restrict__ bias,
    void* __restrict__ Cv)
{
    extern __shared__ __half gsm[];

    const int tid  = threadIdx.x;
    const int lane = tid & 31;
    const int wid  = tid >> 5;
    const int wr   = wid >> 2;
    const int wc   = wid & 3;
    const int tig  = lane & 3;
    const int grp  = lane >> 2;

    const int row0 = blockIdx.y * 128;
    const int col0 = blockIdx.x * 128;

    float acc[4][4][4];
#pragma unroll
    for (int mi = 0; mi < 4; mi++)
#pragma unroll
        for (int ni = 0; ni < 4; ni++)
#pragma unroll
            for (int q = 0; q < 4; q++) acc[mi][ni][q] = 0.f;

    // copy mapping: 128 rows x 4 pieces (of 8 halves) per matrix = 512 pieces
    const int r0c = tid >> 2, j0 = (tid & 3) * 8;
    const int r1c = (tid + 256) >> 2, j1 = ((tid + 256) & 3) * 8;

    auto issue = [&](int it) {
        __half* As = gsm + (it & 3) * GSTG_H;
        __half* Bs = As + 128 * GSTR;
        const int k0 = it * 32;
        cp_async16(&As[r0c * GSTR + j0], A + (size_t)(row0 + r0c) * GK + k0 + j0);
        cp_async16(&As[r1c * GSTR + j1], A + (size_t)(row0 + r1c) * GK + k0 + j1);
        cp_async16(&Bs[r0c * GSTR + j0], W + (size_t)(col0 + r0c) * GK + k0 + j0);
        cp_async16(&Bs[r1c * GSTR + j1], W + (size_t)(col0 + r1c) * GK + k0 + j1);
        cp_commit();
    };

    issue(0); issue(1); issue(2);

    for (int it = 0; it < 32; it++) {
        if (it < 29) cp_wait<2>(); else cp_wait<0>();
        __syncthreads();

        const __half* Ac = gsm + (it & 3) * GSTG_H;
        const __half* Bc = Ac + 128 * GSTR;

        if (it + 3 < 32) issue(it + 3);

#pragma unroll
        for (int kks = 0; kks < 2; kks++) {
            unsigned af[4][4], bf[4][2];
#pragma unroll
            for (int mi = 0; mi < 4; mi++) {
                const int ab = (wr * 64 + mi * 16 + grp) * GSTR + kks * 16 + tig * 2;
                af[mi][0] = *(const unsigned*)&Ac[ab];
                af[mi][1] = *(const unsigned*)&Ac[ab + 8 * GSTR];
                af[mi][2] = *(const unsigned*)&Ac[ab + 8];
                af[mi][3] = *(const unsigned*)&Ac[ab + 8 * GSTR + 8];
            }
#pragma unroll
            for (int ni = 0; ni < 4; ni++) {
                const int bb = (wc * 32 + ni * 8 + grp) * GSTR + kks * 16 + tig * 2;
                bf[ni][0] = *(const unsigned*)&Bc[bb];
                bf[ni][1] = *(const unsigned*)&Bc[bb + 8];
            }
#pragma unroll
            for (int mi = 0; mi < 4; mi++)
#pragma unroll
                for (int ni = 0; ni < 4; ni++)
                    mma_f16(acc[mi][ni], af[mi], bf[ni]);
        }
        __syncthreads();
    }

    // epilogue
#pragma unroll
    for (int mi = 0; mi < 4; mi++) {
        const int r = row0 + wr * 64 + mi * 16 + grp;
#pragma unroll
        for (int ni = 0; ni < 4; ni++) {
            const int c = col0 + wc * 32 + ni * 8 + tig * 2;
            const float b0 = bias[c], b1 = bias[c + 1];
            const float v0 = acc[mi][ni][0] + b0;
            const float v1 = acc[mi][ni][1] + b1;
            const float v2 = acc[mi][ni][2] + b0;
            const float v3 = acc[mi][ni][3] + b1;
            if (OUT_FLOAT) {
                float* C = (float*)Cv;
                float2 w0 = { v0, v1 }, w1 = { v2, v3 };
                *(float2*)(C + (size_t)r * GN + c)       = w0;
                *(float2*)(C + (size_t)(r + 8) * GN + c) = w1;
            } else {
                __half* C = (__half*)Cv;
                *(unsigned*)(C + (size_t)r * GN + c)       = packh2(v0, v1);
                *(unsigned*)(C + (size_t)(r + 8) * GN + c) = packh2(v2, v3);
            }
        }
    }
}

// ---------------------------------------------------------------------------
// FP16 causal flash attention, FA2-style.
// BM=128 (16 q-rows per warp), BN=64 tile, 8 warps.
// Warp owns its rows end-to-end: P stays in registers (S c-frag -> A-frag),
// no inter-warp smem except K/V tiles. K via ldmatrix, V via ldmatrix.trans.
// K/V: 2-stage cp.async double buffer, stride 72 halves.
// Copy mapping per 64x64 tile: 64 rows x 8 pieces (16B) = 512 pieces =
// 256 threads x 2 pieces (halves j and j+32).
// ---------------------------------------------------------------------------
#define HSTR    72                          // halves per smem row
#define KV_H    (64 * HSTR)                 // halves per matrix per stage
#define KVSTG_B (2 * KV_H * 2)              // bytes per stage (K+V) = 18432
#define ATT_SMEM (2 * KVSTG_B)              // 36864 bytes

__global__ __launch_bounds__(256, 2) void attn_f16(
    const __half* __restrict__ Q,
    const __half* __restrict__ K,
    const __half* __restrict__ V,
    __half* __restrict__ O)
{
    extern __shared__ __half hsm[];
    const uint32_t smU = (uint32_t)__cvta_generic_to_shared(hsm);

    const int tid  = threadIdx.x;
    const int lane = tid & 31;
    const int wid  = tid >> 5;
    const int tig  = lane & 3;
    const int grp  = lane >> 2;

    const int qi = (gridDim.x - 1) - blockIdx.x;   // heavy blocks first
    const int h  = blockIdx.y;
    const int b  = blockIdx.z;

    const int ktmax = 2 * qi + 1;

    // copy mapping (64-row tile): row = tid>>2, piece halves (tid&3)*8 and +32
    const int c0r = tid >> 2;
    const int j0h = (tid & 3) * 8;

    const __half* Kbase = K + (size_t)b * SEQ * HID + h * HD;
    const __half* Vbase = V + (size_t)b * SEQ * HID + h * HD;

    auto issue = [&](int kt) {
        __half* Ks = hsm + (kt & 1) * (2 * KV_H);
        __half* Vs = Ks + KV_H;
        const __half* Kb = Kbase + (size_t)kt * 64 * HID;
        const __half* Vb = Vbase + (size_t)kt * 64 * HID;
        cp_async16(&Ks[c0r * HSTR + j0h],      Kb + (size_t)c0r * HID + j0h);
        cp_async16(&Ks[c0r * HSTR + j0h + 32], Kb + (size_t)c0r * HID + j0h + 32);
        cp_async16(&Vs[c0r * HSTR + j0h],      Vb + (size_t)c0r * HID + j0h);
        cp_async16(&Vs[c0r * HSTR + j0h + 32], Vb + (size_t)c0r * HID + j0h + 32);
        cp_commit();
    };

    issue(0);
    issue(1);

    // Q fragments: direct LDG (rows warp-owned), k = d dimension
    const int rowlo = qi * 128 + wid * 16 + grp;
    const __half* Qp = Q + ((size_t)b * SEQ + rowlo) * HID + h * HD;
    unsigned qf[4][4];
#pragma unroll
    for (int kk = 0; kk < 4; kk++) {
        qf[kk][0] = *(const unsigned*)(Qp + kk * 16 + tig * 2);
        qf[kk][1] = *(const unsigned*)(Qp + (size_t)8 * HID + kk * 16 + tig * 2);
        qf[kk][2] = *(const unsigned*)(Qp + kk * 16 + 8 + tig * 2);
        qf[kk][3] = *(const unsigned*)(Qp + (size_t)8 * HID + kk * 16 + 8 + tig * 2);
    }

    // ldmatrix per-lane address components
    const int kRow  = ((lane >> 4) << 3) + (lane & 7);   // K: row within ni-pair
    const int kKoff = ((lane >> 3) & 1) << 3;            // K: k offset 0/8
    const int vRow  = lane & 15;                         // V: m row within 16
    const int vD    = (lane >> 4) << 3;                  // V: d offset 0/8

    float m_i[2] = { -1e30f, -1e30f };
    float l_i[2] = { 0.f, 0.f };
    float o[8][4];
#pragma unroll
    for (int ni = 0; ni < 8; ni++)
#pragma unroll
        for (int q = 0; q < 4; q++) o[ni][q] = 0.f;

    for (int kt = 0; kt <= ktmax; kt++) {
        if (kt < ktmax) cp_wait<1>(); else cp_wait<0>();
        __syncthreads();

        const uint32_t KsU = smU + (kt & 1) * KVSTG_B;
        const uint32_t VsU = KsU + KV_H * 2;

        // ---- S = Q K^T (16 x 64 per warp) ----
        float s[8][4];
#pragma unroll
        for (int ni = 0; ni < 8; ni++)
#pragma unroll
            for (int q = 0; q < 4; q++) s[ni][q] = 0.f;

#pragma unroll
        for (int kk = 0; kk < 4; kk++) {
#pragma unroll
            for (int nib = 0; nib < 8; nib += 2) {
                unsigned m0, m1, m2, m3;
                LDSM_X4(m0, m1, m2, m3,
                        KsU + ((nib * 8 + kRow) * HSTR + kk * 16 + kKoff) * 2);
                unsigned bf0[2] = { m0, m1 };
                unsigned bf1[2] = { m2, m3 };
                mma_f16(s[nib],     qf[kk], bf0);
                mma_f16(s[nib + 1], qf[kk], bf1);
            }
        }

        // scale + causal mask
        if (kt >= 2 * qi) {
#pragma unroll
            for (int ni = 0; ni < 8; ni++) {
                const int c0 = kt * 64 + ni * 8 + tig * 2;
#pragma unroll
                for (int q = 0; q < 4; q++) {
                    const int row = (q < 2) ? rowlo : rowlo + 8;
                    const int col = c0 + (q & 1);
                    s[ni][q] = (col > row) ? -1e30f : s[ni][q] * 0.125f;
                }
            }
        } else {
#pragma unroll
            for (int ni = 0; ni < 8; ni++)
#pragma unroll
                for (int q = 0; q < 4; q++) s[ni][q] *= 0.125f;
        }

        // online softmax (2 rows per thread) + O rescale (register-local)
#pragma unroll
        for (int r = 0; r < 2; r++) {
            const int q0 = 2 * r, q1 = 2 * r + 1;
            float mx = -1e30f;
#pragma unroll
            for (int ni = 0; ni < 8; ni++)
                mx = fmaxf(mx, fmaxf(s[ni][q0], s[ni][q1]));
            mx = fmaxf(mx, __shfl_xor_sync(0xffffffffu, mx, 1));
            mx = fmaxf(mx, __shfl_xor_sync(0xffffffffu, mx, 2));
            const float m_new = fmaxf(m_i[r], mx);
            const float al    = __expf(m_i[r] - m_new);
            float sum = 0.f;
#pragma unroll
            for (int ni = 0; ni < 8; ni++) {
                const float p0 = __expf(s[ni][q0] - m_new);
                const float p1 = __expf(s[ni][q1] - m_new);
                s[ni][q0] = p0; s[ni][q1] = p1;
                sum += p0 + p1;
            }
            sum += __shfl_xor_sync(0xffffffffu, sum, 1);
            sum += __shfl_xor_sync(0xffffffffu, sum, 2);
            l_i[r] = l_i[r] * al + sum;
            m_i[r] = m_new;
#pragma unroll
            for (int ni = 0; ni < 8; ni++) {
                o[ni][q0] *= al;
                o[ni][q1] *= al;
            }
        }

        // ---- O += P V (P from registers, V via ldmatrix.trans) ----
#pragma unroll
        for (int kkm = 0; kkm < 4; kkm++) {
            unsigned a[4];
            a[0] = packh2(s[2 * kkm][0],     s[2 * kkm][1]);
            a[1] = packh2(s[2 * kkm][2],     s[2 * kkm][3]);
            a[2] = packh2(s[2 * kkm + 1][0], s[2 * kkm + 1][1]);
            a[3] = packh2(s[2 * kkm + 1][2], s[2 * kkm + 1][3]);
#pragma unroll
            for (int nidb = 0; nidb < 8; nidb += 2) {
                unsigned m0, m1, m2, m3;
                LDSM_X4T(m0, m1, m2, m3,
                         VsU + ((kkm * 16 + vRow) * HSTR + nidb * 8 + vD) * 2);
                unsigned bf0[2] = { m0, m1 };
                unsigned bf1[2] = { m2, m3 };
                mma_f16(o[nidb],     a, bf0);
                mma_f16(o[nidb + 1], a, bf1);
            }
        }
        __syncthreads();   // all warps done reading stage (kt&1)

        if (kt + 2 <= ktmax) issue(kt + 2);
    }

    // epilogue: divide by l, store fp16
    const float inv0 = 1.f / l_i[0];
    const float inv1 = 1.f / l_i[1];
    __half* Ob = O + ((size_t)b * SEQ + rowlo) * HID + h * HD;
#pragma unroll
    for (int ni = 0; ni < 8; ni++) {
        const int d = ni * 8 + tig * 2;
        *(unsigned*)(Ob + d)                    = packh2(o[ni][0] * inv0, o[ni][1] * inv0);
        *(unsigned*)(Ob + (size_t)8 * HID + d)  = packh2(o[ni][2] * inv1, o[ni][3] * inv1);
    }
}

// ---------------------------------------------------------------------------
extern "C" void kernel_launch(void* const* d_in, const int* in_sizes, int n_in,
                              void* d_out, int out_size)
{
    const float* query = (const float*)d_in[0];
    const float* key   = (const float*)d_in[1];
    const float* val   = (const float*)d_in[2];
    // d_in[3] = attn_mask (tril causal) — implemented directly in attn_f16
    const float* Wq = (const float*)d_in[4];
    const float* bq = (const float*)d_in[5];
    const float* Wk = (const float*)d_in[6];
    const float* bk = (const float*)d_in[7];
    const float* Wv = (const float*)d_in[8];
    const float* bv = (const float*)d_in[9];
    const float* Wo = (const float*)d_in[10];
    const float* bo = (const float*)d_in[11];
    float* out = (float*)d_out;

    void *pQ, *pK, *pV, *pAO, *pXq, *pXk, *pXv, *pWq, *pWk, *pWv, *pWo;
    cudaGetSymbolAddress(&pQ,  g_Q);
    cudaGetSymbolAddress(&pK,  g_K);
    cudaGetSymbolAddress(&pV,  g_V);
    cudaGetSymbolAddress(&pAO, g_AO);
    cudaGetSymbolAddress(&pXq, g_Xq);
    cudaGetSymbolAddress(&pXk, g_Xk);
    cudaGetSymbolAddress(&pXv, g_Xv);
    cudaGetSymbolAddress(&pWq, g_Wq);
    cudaGetSymbolAddress(&pWk, g_Wk);
    cudaGetSymbolAddress(&pWv, g_Wv);
    cudaGetSymbolAddress(&pWo, g_Wo);

    cudaFuncSetAttribute(gemm_f16<false>,
                         cudaFuncAttributeMaxDynamicSharedMemorySize, GEMM_SMEM);
    cudaFuncSetAttribute(gemm_f16<true>,
                         cudaFuncAttributeMaxDynamicSharedMemorySize, GEMM_SMEM);
    cudaFuncSetAttribute(attn_f16,
                         cudaFuncAttributeMaxDynamicSharedMemorySize, ATT_SMEM);

    // pre-pass: convert inputs to fp16
    const int nX8 = MTOT * HID / 8;
    const int nW8 = HID * HID / 8;
    cvt_h_kernel<<<(nX8 + 255) / 256, 256>>>(query, (__half*)pXq, nX8);
    cvt_h_kernel<<<(nX8 + 255) / 256, 256>>>(key,   (__half*)pXk, nX8);
    cvt_h_kernel<<<(nX8 + 255) / 256, 256>>>(val,   (__half*)pXv, nX8);
    cvt_h_kernel<<<(nW8 + 255) / 256, 256>>>(Wq, (__half*)pWq, nW8);
    cvt_h_kernel<<<(nW8 + 255) / 256, 256>>>(Wk, (__half*)pWk, nW8);
    cvt_h_kernel<<<(nW8 + 255) / 256, 256>>>(Wv, (__half*)pWv, nW8);
    cvt_h_kernel<<<(nW8 + 255) / 256, 256>>>(Wo, (__half*)pWo, nW8);

    const dim3 ggrid(GN / 128, MTOT / 128);    // (8, 64)
    gemm_f16<false><<<ggrid, 256, GEMM_SMEM>>>((const __half*)pXq, (const __half*)pWq, bq, pQ);
    gemm_f16<false><<<ggrid, 256, GEMM_SMEM>>>((const __half*)pXk, (const __half*)pWk, bk, pK);
    gemm_f16<false><<<ggrid, 256, GEMM_SMEM>>>((const __half*)pXv, (const __half*)pWv, bv, pV);

    const dim3 agrid(SEQ / 128, NH, BATCH);     // (16, 16, 4)
    attn_f16<<<agrid, 256, ATT_SMEM>>>((const __half*)pQ, (const __half*)pK,
                                       (const __half*)pV, (__half*)pAO);

    gemm_f16<true><<<ggrid, 256, GEMM_SMEM>>>((const __half*)pAO, (const __half*)pWo, bo, out);
}

// round 10
// speedup vs baseline: 6.6993x; 1.1584x over previous
#include <cuda_runtime.h>
#include <cuda_fp16.h>
#include <math.h>
#include <stdint.h>

// Problem constants
#define BATCH 4
#define SEQ   2048
#define HID   1024
#define NH    16
#define HD    64
#define MTOT  (BATCH * SEQ)   // 8192
#define GK    1024
#define GN    1024

// Scratch (device globals: no runtime allocation allowed)
__device__ __half g_Q [MTOT * HID];
__device__ __half g_K [MTOT * HID];
__device__ __half g_V [MTOT * HID];
__device__ __half g_AO[MTOT * HID];
// fp16 copies of inputs
__device__ __half g_Xq[MTOT * HID];
__device__ __half g_Xk[MTOT * HID];
__device__ __half g_Xv[MTOT * HID];
__device__ __half g_Wq[HID * HID];
__device__ __half g_Wk[HID * HID];
__device__ __half g_Wv[HID * HID];
__device__ __half g_Wo[HID * HID];

__device__ __forceinline__ void mma_f16(float* d, const unsigned* a, const unsigned* b) {
    asm volatile(
        "mma.sync.aligned.m16n8k16.row.col.f32.f16.f16.f32 "
        "{%0,%1,%2,%3}, {%4,%5,%6,%7}, {%8,%9}, {%0,%1,%2,%3};\n"
        : "+f"(d[0]), "+f"(d[1]), "+f"(d[2]), "+f"(d[3])
        : "r"(a[0]), "r"(a[1]), "r"(a[2]), "r"(a[3]),
          "r"(b[0]), "r"(b[1]));
}

__device__ __forceinline__ void cp_async16(void* dst, const void* src) {
    unsigned d = (unsigned)__cvta_generic_to_shared(dst);
    asm volatile("cp.async.cg.shared.global [%0], [%1], 16;\n" :: "r"(d), "l"(src));
}
__device__ __forceinline__ void cp_commit() {
    asm volatile("cp.async.commit_group;\n");
}
template <int N>
__device__ __forceinline__ void cp_wait() {
    asm volatile("cp.async.wait_group %0;\n" :: "n"(N));
}

#define LDSM_X4(R0, R1, R2, R3, ADDR) \
    asm volatile("ldmatrix.sync.aligned.m8n8.x4.shared.b16 {%0,%1,%2,%3}, [%4];" \
        : "=r"(R0), "=r"(R1), "=r"(R2), "=r"(R3) : "r"(ADDR))
#define LDSM_X4T(R0, R1, R2, R3, ADDR) \
    asm volatile("ldmatrix.sync.aligned.m8n8.x4.trans.shared.b16 {%0,%1,%2,%3}, [%4];" \
        : "=r"(R0), "=r"(R1), "=r"(R2), "=r"(R3) : "r"(ADDR))

__device__ __forceinline__ unsigned packh2(float lo, float hi) {
    __half2 h = __floats2half2_rn(lo, hi);
    return *reinterpret_cast<unsigned*>(&h);
}

// ---------------------------------------------------------------------------
// Pre-pass: fp32 -> fp16 (RN), fused across tensors via blockIdx.y.
// ---------------------------------------------------------------------------
__global__ __launch_bounds__(256) void cvt_h3(
    const float* s0, const float* s1, const float* s2,
    __half* d0, __half* d1, __half* d2, int n8)
{
    const float* src = (blockIdx.y == 0) ? s0 : (blockIdx.y == 1) ? s1 : s2;
    __half*      dst = (blockIdx.y == 0) ? d0 : (blockIdx.y == 1) ? d1 : d2;
    const int i = blockIdx.x * blockDim.x + threadIdx.x;
    if (i < n8) {
        float4 v0 = ((const float4*)src)[2 * i];
        float4 v1 = ((const float4*)src)[2 * i + 1];
        unsigned u[4];
        u[0] = packh2(v0.x, v0.y);
        u[1] = packh2(v0.z, v0.w);
        u[2] = packh2(v1.x, v1.y);
        u[3] = packh2(v1.z, v1.w);
        ((uint4*)dst)[i] = *(uint4*)u;
    }
}

__global__ __launch_bounds__(256) void cvt_h4(
    const float* s0, const float* s1, const float* s2, const float* s3,
    __half* d0, __half* d1, __half* d2, __half* d3, int n8)
{
    const float* src = (blockIdx.y == 0) ? s0 : (blockIdx.y == 1) ? s1
                     : (blockIdx.y == 2) ? s2 : s3;
    __half*      dst = (blockIdx.y == 0) ? d0 : (blockIdx.y == 1) ? d1
                     : (blockIdx.y == 2) ? d2 : d3;
    const int i = blockIdx.x * blockDim.x + threadIdx.x;
    if (i < n8) {
        float4 v0 = ((const float4*)src)[2 * i];
        float4 v1 = ((const float4*)src)[2 * i + 1];
        unsigned u[4];
        u[0] = packh2(v0.x, v0.y);
        u[1] = packh2(v0.z, v0.w);
        u[2] = packh2(v1.x, v1.y);
        u[3] = packh2(v1.z, v1.w);
        ((uint4*)dst)[i] = *(uint4*)u;
    }
}

// ---------------------------------------------------------------------------
// FP16 GEMM body: C[M,1024] = A[M,1024] @ W[1024,1024]^T + bias
// 128x128 tile, BK=32, 8 warps (2x4), 4-stage cp.async, ldmatrix frag loads.
// ---------------------------------------------------------------------------
#define GSTR   40                          // halves per smem row
#define GSTG_H (2 * 128 * GSTR)            // halves per stage (A+B) = 10240
#define GEMM_SMEM (4 * GSTG_H * 2)         // 81920 bytes

template <bool OUT_FLOAT>
__device__ __forceinline__ void gemm_body(
    const __half* __restrict__ A,
    const __half* __restrict__ W,
    const float* __restrict__ bias,
    void* __restrict__ Cv,
    __half* gsm, int row0, int col0)
{
    const uint32_t smU = (uint32_t)__cvta_generic_to_shared(gsm);
    const int tid  = threadIdx.x;
    const int lane = tid & 31;
    const int wid  = tid >> 5;
    const int wr   = wid >> 2;
    const int wc   = wid & 3;
    const int tig  = lane & 3;
    const int grp  = lane >> 2;

    float acc[4][4][4];
#pragma unroll
    for (int mi = 0; mi < 4; mi++)
#pragma unroll
        for (int ni = 0; ni < 4; ni++)
#pragma unroll
            for (int q = 0; q < 4; q++) acc[mi][ni][q] = 0.f;

    // copy mapping: 128 rows x 4 pieces (of 8 halves) per matrix = 512 pieces
    const int r0c = tid >> 2, j0 = (tid & 3) * 8;
    const int r1c = (tid + 256) >> 2, j1 = ((tid + 256) & 3) * 8;

    auto issue = [&](int it) {
        __half* As = gsm + (it & 3) * GSTG_H;
        __half* Bs = As + 128 * GSTR;
        const int k0 = it * 32;
        cp_async16(&As[r0c * GSTR + j0], A + (size_t)(row0 + r0c) * GK + k0 + j0);
        cp_async16(&As[r1c * GSTR + j1], A + (size_t)(row0 + r1c) * GK + k0 + j1);
        cp_async16(&Bs[r0c * GSTR + j0], W + (size_t)(col0 + r0c) * GK + k0 + j0);
        cp_async16(&Bs[r1c * GSTR + j1], W + (size_t)(col0 + r1c) * GK + k0 + j1);
        cp_commit();
    };

    issue(0); issue(1); issue(2);

    // ldmatrix lane address components
    const int aRow  = (lane & 7) + ((lane >> 3) & 1) * 8;  // A: (m0k0)(m8k0)(m0k8)(m8k8)
    const int aKoff = (lane >> 4) << 3;
    const int bRow  = ((lane >> 4) << 3) + (lane & 7);     // B: (n0k0)(n0k8)(n8k0)(n8k8)
    const int bKoff = ((lane >> 3) & 1) << 3;

    for (int it = 0; it < 32; it++) {
        if (it < 29) cp_wait<2>(); else cp_wait<0>();
        __syncthreads();

        const uint32_t AcU = smU + ((it & 3) * GSTG_H) * 2;
        const uint32_t BcU = AcU + (128 * GSTR) * 2;

        if (it + 3 < 32) issue(it + 3);

#pragma unroll
        for (int kks = 0; kks < 2; kks++) {
            unsigned af[4][4], bf[4][2];
#pragma unroll
            for (int mi = 0; mi < 4; mi++) {
                LDSM_X4(af[mi][0], af[mi][1], af[mi][2], af[mi][3],
                        AcU + (((wr * 64 + mi * 16 + aRow) * GSTR) + kks * 16 + aKoff) * 2);
            }
#pragma unroll
            for (int nb = 0; nb < 2; nb++) {
                unsigned m0, m1, m2, m3;
                LDSM_X4(m0, m1, m2, m3,
                        BcU + (((wc * 32 + nb * 16 + bRow) * GSTR) + kks * 16 + bKoff) * 2);
                bf[2 * nb][0] = m0; bf[2 * nb][1] = m1;
                bf[2 * nb + 1][0] = m2; bf[2 * nb + 1][1] = m3;
            }
#pragma unroll
            for (int mi = 0; mi < 4; mi++)
#pragma unroll
                for (int ni = 0; ni < 4; ni++)
                    mma_f16(acc[mi][ni], af[mi], bf[ni]);
        }
        __syncthreads();
    }

    // epilogue
#pragma unroll
    for (int mi = 0; mi < 4; mi++) {
        const int r = row0 + wr * 64 + mi * 16 + grp;
#pragma unroll
        for (int ni = 0; ni < 4; ni++) {
            const int c = col0 + wc * 32 + ni * 8 + tig * 2;
            const float b0 = bias[c], b1 = bias[c + 1];
            const float v0 = acc[mi][ni][0] + b0;
            const float v1 = acc[mi][ni][1] + b1;
            const float v2 = acc[mi][ni][2] + b0;
            const float v3 = acc[mi][ni][3] + b1;
            if (OUT_FLOAT) {
                float* C = (float*)Cv;
                float2 w0 = { v0, v1 }, w1 = { v2, v3 };
                *(float2*)(C + (size_t)r * GN + c)       = w0;
                *(float2*)(C + (size_t)(r + 8) * GN + c) = w1;
            } else {
                __half* C = (__half*)Cv;
                *(unsigned*)(C + (size_t)r * GN + c)       = packh2(v0, v1);
                *(unsigned*)(C + (size_t)(r + 8) * GN + c) = packh2(v2, v3);
            }
        }
    }
}

// Fused Q/K/V projection GEMMs (blockIdx.z selects tensor)
__global__ __launch_bounds__(256, 2) void gemm_qkv(
    const __half* X0, const __half* X1, const __half* X2,
    const __half* W0, const __half* W1, const __half* W2,
    const float* b0, const float* b1, const float* b2,
    __half* C0, __half* C1, __half* C2)
{
    extern __shared__ __half gsm[];
    const int z = blockIdx.z;
    const __half* A = (z == 0) ? X0 : (z == 1) ? X1 : X2;
    const __half* W = (z == 0) ? W0 : (z == 1) ? W1 : W2;
    const float*  b = (z == 0) ? b0 : (z == 1) ? b1 : b2;
    __half*       C = (z == 0) ? C0 : (z == 1) ? C1 : C2;
    gemm_body<false>(A, W, b, C, gsm, blockIdx.y * 128, blockIdx.x * 128);
}

// Output projection GEMM (fp32 out)
__global__ __launch_bounds__(256, 2) void gemm_wo(
    const __half* __restrict__ A, const __half* __restrict__ W,
    const float* __restrict__ bias, float* __restrict__ C)
{
    extern __shared__ __half gsm[];
    gemm_body<true>(A, W, bias, C, gsm, blockIdx.y * 128, blockIdx.x * 128);
}

// ---------------------------------------------------------------------------
// FP16 causal flash attention, FA2-style (exp2 domain softmax).
// BM=128 (16 q-rows per warp), BN=64, 8 warps, 2-stage cp.async K/V.
// ---------------------------------------------------------------------------
#define HSTR    72                          // halves per smem row
#define KV_H    (64 * HSTR)                 // halves per matrix per stage
#define KVSTG_B (2 * KV_H * 2)              // bytes per stage (K+V) = 18432
#define ATT_SMEM (2 * KVSTG_B)              // 36864 bytes
#define SCALE_LOG2E 0.1803368801111f        // 0.125 * log2(e)

__global__ __launch_bounds__(256, 2) void attn_f16(
    const __half* __restrict__ Q,
    const __half* __restrict__ K,
    const __half* __restrict__ V,
    __half* __restrict__ O)
{
    extern __shared__ __half hsm[];
    const uint32_t smU = (uint32_t)__cvta_generic_to_shared(hsm);

    const int tid  = threadIdx.x;
    const int lane = tid & 31;
    const int wid  = tid >> 5;
    const int tig  = lane & 3;
    const int grp  = lane >> 2;

    const int qi = (gridDim.x - 1) - blockIdx.x;   // heavy blocks first
    const int h  = blockIdx.y;
    const int b  = blockIdx.z;

    const int ktmax = 2 * qi + 1;

    // copy mapping (64-row tile): row = tid>>2, piece halves (tid&3)*8 and +32
    const int c0r = tid >> 2;
    const int j0h = (tid & 3) * 8;

    const __half* Kbase = K + (size_t)b * SEQ * HID + h * HD;
    const __half* Vbase = V + (size_t)b * SEQ * HID + h * HD;

    auto issue = [&](int kt) {
        __half* Ks = hsm + (kt & 1) * (2 * KV_H);
        __half* Vs = Ks + KV_H;
        const __half* Kb = Kbase + (size_t)kt * 64 * HID;
        const __half* Vb = Vbase + (size_t)kt * 64 * HID;
        cp_async16(&Ks[c0r * HSTR + j0h],      Kb + (size_t)c0r * HID + j0h);
        cp_async16(&Ks[c0r * HSTR + j0h + 32], Kb + (size_t)c0r * HID + j0h + 32);
        cp_async16(&Vs[c0r * HSTR + j0h],      Vb + (size_t)c0r * HID + j0h);
        cp_async16(&Vs[c0r * HSTR + j0h + 32], Vb + (size_t)c0r * HID + j0h + 32);
        cp_commit();
    };

    issue(0);
    issue(1);

    // Q fragments: direct LDG (rows warp-owned)
    const int rowlo = qi * 128 + wid * 16 + grp;
    const __half* Qp = Q + ((size_t)b * SEQ + rowlo) * HID + h * HD;
    unsigned qf[4][4];
#pragma unroll
    for (int kk = 0; kk < 4; kk++) {
        qf[kk][0] = *(const unsigned*)(Qp + kk * 16 + tig * 2);
        qf[kk][1] = *(const unsigned*)(Qp + (size_t)8 * HID + kk * 16 + tig * 2);
        qf[kk][2] = *(const unsigned*)(Qp + kk * 16 + 8 + tig * 2);
        qf[kk][3] = *(const unsigned*)(Qp + (size_t)8 * HID + kk * 16 + 8 + tig * 2);
    }

    // ldmatrix per-lane address components
    const int kRow  = ((lane >> 4) << 3) + (lane & 7);
    const int kKoff = ((lane >> 3) & 1) << 3;
    const int vRow  = lane & 15;
    const int vD    = (lane >> 4) << 3;

    float m_i[2] = { -1e30f, -1e30f };
    float l_i[2] = { 0.f, 0.f };
    float o[8][4];
#pragma unroll
    for (int ni = 0; ni < 8; ni++)
#pragma unroll
        for (int q = 0; q < 4; q++) o[ni][q] = 0.f;

    for (int kt = 0; kt <= ktmax; kt++) {
        if (kt < ktmax) cp_wait<1>(); else cp_wait<0>();
        __syncthreads();

        const uint32_t KsU = smU + (kt & 1) * KVSTG_B;
        const uint32_t VsU = KsU + KV_H * 2;

        // ---- S = Q K^T (16 x 64 per warp) ----
        float s[8][4];
#pragma unroll
        for (int ni = 0; ni < 8; ni++)
#pragma unroll
            for (int q = 0; q < 4; q++) s[ni][q] = 0.f;

#pragma unroll
        for (int kk = 0; kk < 4; kk++) {
#pragma unroll
            for (int nib = 0; nib < 8; nib += 2) {
                unsigned m0, m1, m2, m3;
                LDSM_X4(m0, m1, m2, m3,
                        KsU + ((nib * 8 + kRow) * HSTR + kk * 16 + kKoff) * 2);
                unsigned bf0[2] = { m0, m1 };
                unsigned bf1[2] = { m2, m3 };
                mma_f16(s[nib],     qf[kk], bf0);
                mma_f16(s[nib + 1], qf[kk], bf1);
            }
        }

        // scale into exp2 domain + causal mask
        if (kt >= 2 * qi) {
#pragma unroll
            for (int ni = 0; ni < 8; ni++) {
                const int c0 = kt * 64 + ni * 8 + tig * 2;
#pragma unroll
                for (int q = 0; q < 4; q++) {
                    const int row = (q < 2) ? rowlo : rowlo + 8;
                    const int col = c0 + (q & 1);
                    s[ni][q] = (col > row) ? -1e30f : s[ni][q] * SCALE_LOG2E;
                }
            }
        } else {
#pragma unroll
            for (int ni = 0; ni < 8; ni++)
#pragma unroll
                for (int q = 0; q < 4; q++) s[ni][q] *= SCALE_LOG2E;
        }

        // online softmax (exp2 domain; 2 rows per thread) + O rescale
#pragma unroll
        for (int r = 0; r < 2; r++) {
            const int q0 = 2 * r, q1 = 2 * r + 1;
            float mx = -1e30f;
#pragma unroll
            for (int ni = 0; ni < 8; ni++)
                mx = fmaxf(mx, fmaxf(s[ni][q0], s[ni][q1]));
            mx = fmaxf(mx, __shfl_xor_sync(0xffffffffu, mx, 1));
            mx = fmaxf(mx, __shfl_xor_sync(0xffffffffu, mx, 2));
            const float m_new = fmaxf(m_i[r], mx);
            const float al    = exp2f(m_i[r] - m_new);
            float sum = 0.f;
#pragma unroll
            for (int ni = 0; ni < 8; ni++) {
                const float p0 = exp2f(s[ni][q0] - m_new);
                const float p1 = exp2f(s[ni][q1] - m_new);
                s[ni][q0] = p0; s[ni][q1] = p1;
                sum += p0 + p1;
            }
            sum += __shfl_xor_sync(0xffffffffu, sum, 1);
            sum += __shfl_xor_sync(0xffffffffu, sum, 2);
            l_i[r] = l_i[r] * al + sum;
            m_i[r] = m_new;
#pragma unroll
            for (int ni = 0; ni < 8; ni++) {
                o[ni][q0] *= al;
                o[ni][q1] *= al;
            }
        }

        // ---- O += P V (P from registers, V via ldmatrix.trans) ----
#pragma unroll
        for (int kkm = 0; kkm < 4; kkm++) {
            unsigned a[4];
            a[0] = packh2(s[2 * kkm][0],     s[2 * kkm][1]);
            a[1] = packh2(s[2 * kkm][2],     s[2 * kkm][3]);
            a[2] = packh2(s[2 * kkm + 1][0], s[2 * kkm + 1][1]);
            a[3] = packh2(s[2 * kkm + 1][2], s[2 * kkm + 1][3]);
#pragma unroll
            for (int nidb = 0; nidb < 8; nidb += 2) {
                unsigned m0, m1, m2, m3;
                LDSM_X4T(m0, m1, m2, m3,
                         VsU + ((kkm * 16 + vRow) * HSTR + nidb * 8 + vD) * 2);
                unsigned bf0[2] = { m0, m1 };
                unsigned bf1[2] = { m2, m3 };
                mma_f16(o[nidb],     a, bf0);
                mma_f16(o[nidb + 1], a, bf1);
            }
        }
        __syncthreads();   // all warps done reading stage (kt&1)

        if (kt + 2 <= ktmax) issue(kt + 2);
    }

    // epilogue: divide by l, store fp16
    const float inv0 = 1.f / l_i[0];
    const float inv1 = 1.f / l_i[1];
    __half* Ob = O + ((size_t)b * SEQ + rowlo) * HID + h * HD;
#pragma unroll
    for (int ni = 0; ni < 8; ni++) {
        const int d = ni * 8 + tig * 2;
        *(unsigned*)(Ob + d)                    = packh2(o[ni][0] * inv0, o[ni][1] * inv0);
        *(unsigned*)(Ob + (size_t)8 * HID + d)  = packh2(o[ni][2] * inv1, o[ni][3] * inv1);
    }
}

// ---------------------------------------------------------------------------
extern "C" void kernel_launch(void* const* d_in, const int* in_sizes, int n_in,
                              void* d_out, int out_size)
{
    const float* query = (const float*)d_in[0];
    const float* key   = (const float*)d_in[1];
    const float* val   = (const float*)d_in[2];
    // d_in[3] = attn_mask (tril causal) — implemented directly in attn_f16
    const float* Wq = (const float*)d_in[4];
    const float* bq = (const float*)d_in[5];
    const float* Wk = (const float*)d_in[6];
    const float* bk = (const float*)d_in[7];
    const float* Wv = (const float*)d_in[8];
    const float* bv = (const float*)d_in[9];
    const float* Wo = (const float*)d_in[10];
    const float* bo = (const float*)d_in[11];
    float* out = (float*)d_out;

    void *pQ, *pK, *pV, *pAO, *pXq, *pXk, *pXv, *pWq, *pWk, *pWv, *pWo;
    cudaGetSymbolAddress(&pQ,  g_Q);
    cudaGetSymbolAddress(&pK,  g_K);
    cudaGetSymbolAddress(&pV,  g_V);
    cudaGetSymbolAddress(&pAO, g_AO);
    cudaGetSymbolAddress(&pXq, g_Xq);
    cudaGetSymbolAddress(&pXk, g_Xk);
    cudaGetSymbolAddress(&pXv, g_Xv);
    cudaGetSymbolAddress(&pWq, g_Wq);
    cudaGetSymbolAddress(&pWk, g_Wk);
    cudaGetSymbolAddress(&pWv, g_Wv);
    cudaGetSymbolAddress(&pWo, g_Wo);

    cudaFuncSetAttribute(gemm_qkv,
                         cudaFuncAttributeMaxDynamicSharedMemorySize, GEMM_SMEM);
    cudaFuncSetAttribute(gemm_wo,
                         cudaFuncAttributeMaxDynamicSharedMemorySize, GEMM_SMEM);
    cudaFuncSetAttribute(attn_f16,
                         cudaFuncAttributeMaxDynamicSharedMemorySize, ATT_SMEM);

    // pre-pass: convert inputs to fp16 (2 fused launches)
    const int nX8 = MTOT * HID / 8;
    const int nW8 = HID * HID / 8;
    {
        dim3 g3((nX8 + 255) / 256, 3);
        cvt_h3<<<g3, 256>>>(query, key, val,
                            (__half*)pXq, (__half*)pXk, (__half*)pXv, nX8);
        dim3 g4((nW8 + 255) / 256, 4);
        cvt_h4<<<g4, 256>>>(Wq, Wk, Wv, Wo,
                            (__half*)pWq, (__half*)pWk, (__half*)pWv, (__half*)pWo, nW8);
    }

    const dim3 gqkv(GN / 128, MTOT / 128, 3);  // (8, 64, 3)
    gemm_qkv<<<gqkv, 256, GEMM_SMEM>>>(
        (const __half*)pXq, (const __half*)pXk, (const __half*)pXv,
        (const __half*)pWq, (const __half*)pWk, (const __half*)pWv,
        bq, bk, bv,
        (__half*)pQ, (__half*)pK, (__half*)pV);

    const dim3 agrid(SEQ / 128, NH, BATCH);     // (16, 16, 4)
    attn_f16<<<agrid, 256, ATT_SMEM>>>((const __half*)pQ, (const __half*)pK,
                                       (const __half*)pV, (__half*)pAO);

    const dim3 gwo(GN / 128, MTOT / 128);       // (8, 64)
    gemm_wo<<<gwo, 256, GEMM_SMEM>>>((const __half*)pAO, (const __half*)pWo, bo, out);
}

// round 11
// speedup vs baseline: 7.1044x; 1.0605x over previous
#include <cuda_runtime.h>
#include <cuda_fp16.h>
#include <math.h>
#include <stdint.h>

// Problem constants
#define BATCH 4
#define SEQ   2048
#define HID   1024
#define NH    16
#define HD    64
#define MTOT  (BATCH * SEQ)   // 8192
#define GK    1024
#define GN    1024

// Scratch (device globals: no runtime allocation allowed)
__device__ __half g_Q [MTOT * HID];
__device__ __half g_K [MTOT * HID];
__device__ __half g_V [MTOT * HID];
__device__ __half g_AO[MTOT * HID];
// fp16 copies of inputs
__device__ __half g_Xq[MTOT * HID];
__device__ __half g_Xk[MTOT * HID];
__device__ __half g_Xv[MTOT * HID];
__device__ __half g_Wq[HID * HID];
__device__ __half g_Wk[HID * HID];
__device__ __half g_Wv[HID * HID];
__device__ __half g_Wo[HID * HID];

#define SCALE_LOG2E 0.1803368801111f        // 0.125 * log2(e)

__device__ __forceinline__ void mma_f16(float* d, const unsigned* a, const unsigned* b) {
    asm volatile(
        "mma.sync.aligned.m16n8k16.row.col.f32.f16.f16.f32 "
        "{%0,%1,%2,%3}, {%4,%5,%6,%7}, {%8,%9}, {%0,%1,%2,%3};\n"
        : "+f"(d[0]), "+f"(d[1]), "+f"(d[2]), "+f"(d[3])
        : "r"(a[0]), "r"(a[1]), "r"(a[2]), "r"(a[3]),
          "r"(b[0]), "r"(b[1]));
}

__device__ __forceinline__ void cp_async16(void* dst, const void* src) {
    unsigned d = (unsigned)__cvta_generic_to_shared(dst);
    asm volatile("cp.async.cg.shared.global [%0], [%1], 16;\n" :: "r"(d), "l"(src));
}
__device__ __forceinline__ void cp_commit() {
    asm volatile("cp.async.commit_group;\n");
}
template <int N>
__device__ __forceinline__ void cp_wait() {
    asm volatile("cp.async.wait_group %0;\n" :: "n"(N));
}

#define LDSM_X4(R0, R1, R2, R3, ADDR) \
    asm volatile("ldmatrix.sync.aligned.m8n8.x4.shared.b16 {%0,%1,%2,%3}, [%4];" \
        : "=r"(R0), "=r"(R1), "=r"(R2), "=r"(R3) : "r"(ADDR))
#define LDSM_X4T(R0, R1, R2, R3, ADDR) \
    asm volatile("ldmatrix.sync.aligned.m8n8.x4.trans.shared.b16 {%0,%1,%2,%3}, [%4];" \
        : "=r"(R0), "=r"(R1), "=r"(R2), "=r"(R3) : "r"(ADDR))

__device__ __forceinline__ unsigned packh2(float lo, float hi) {
    __half2 h = __floats2half2_rn(lo, hi);
    return *reinterpret_cast<unsigned*>(&h);
}
__device__ __forceinline__ unsigned ex2h2(unsigned x) {
    unsigned r;
    asm("ex2.approx.f16x2 %0, %1;" : "=r"(r) : "r"(x));
    return r;
}
__device__ __forceinline__ unsigned hadd2u(unsigned a, unsigned b) {
    __half2 r = __hadd2(*reinterpret_cast<__half2*>(&a),
                        *reinterpret_cast<__half2*>(&b));
    return *reinterpret_cast<unsigned*>(&r);
}

// ---------------------------------------------------------------------------
// Pre-pass: fp32 -> fp16 (RN), fused across tensors via blockIdx.y.
// ---------------------------------------------------------------------------
__global__ __launch_bounds__(256) void cvt_h3(
    const float* s0, const float* s1, const float* s2,
    __half* d0, __half* d1, __half* d2, int n8)
{
    const float* src = (blockIdx.y == 0) ? s0 : (blockIdx.y == 1) ? s1 : s2;
    __half*      dst = (blockIdx.y == 0) ? d0 : (blockIdx.y == 1) ? d1 : d2;
    const int i = blockIdx.x * blockDim.x + threadIdx.x;
    if (i < n8) {
        float4 v0 = ((const float4*)src)[2 * i];
        float4 v1 = ((const float4*)src)[2 * i + 1];
        unsigned u[4];
        u[0] = packh2(v0.x, v0.y);
        u[1] = packh2(v0.z, v0.w);
        u[2] = packh2(v1.x, v1.y);
        u[3] = packh2(v1.z, v1.w);
        ((uint4*)dst)[i] = *(uint4*)u;
    }
}

__global__ __launch_bounds__(256) void cvt_h4(
    const float* s0, const float* s1, const float* s2, const float* s3,
    __half* d0, __half* d1, __half* d2, __half* d3, int n8)
{
    const float* src = (blockIdx.y == 0) ? s0 : (blockIdx.y == 1) ? s1
                     : (blockIdx.y == 2) ? s2 : s3;
    __half*      dst = (blockIdx.y == 0) ? d0 : (blockIdx.y == 1) ? d1
                     : (blockIdx.y == 2) ? d2 : d3;
    const int i = blockIdx.x * blockDim.x + threadIdx.x;
    if (i < n8) {
        float4 v0 = ((const float4*)src)[2 * i];
        float4 v1 = ((const float4*)src)[2 * i + 1];
        unsigned u[4];
        u[0] = packh2(v0.x, v0.y);
        u[1] = packh2(v0.z, v0.w);
        u[2] = packh2(v1.x, v1.y);
        u[3] = packh2(v1.z, v1.w);
        ((uint4*)dst)[i] = *(uint4*)u;
    }
}

// ---------------------------------------------------------------------------
// FP16 GEMM body: C[M,1024] = A[M,1024] @ W[1024,1024]^T + bias
// 128x128 tile, BK=32, 8 warps (2x4), 4-stage cp.async, ldmatrix frag loads.
// Single __syncthreads per k-iteration (stage it+3 == stage it-1, whose last
// reader finished before this iteration's barrier).
// oscale applied to fp16 outputs (used to pre-scale Q by 0.125*log2e).
// ---------------------------------------------------------------------------
#define GSTR   40                          // halves per smem row
#define GSTG_H (2 * 128 * GSTR)            // halves per stage (A+B) = 10240
#define GEMM_SMEM (4 * GSTG_H * 2)         // 81920 bytes

template <bool OUT_FLOAT>
__device__ __forceinline__ void gemm_body(
    const __half* __restrict__ A,
    const __half* __restrict__ W,
    const float* __restrict__ bias,
    void* __restrict__ Cv,
    __half* gsm, int row0, int col0, float oscale)
{
    const uint32_t smU = (uint32_t)__cvta_generic_to_shared(gsm);
    const int tid  = threadIdx.x;
    const int lane = tid & 31;
    const int wid  = tid >> 5;
    const int wr   = wid >> 2;
    const int wc   = wid & 3;
    const int tig  = lane & 3;
    const int grp  = lane >> 2;

    float acc[4][4][4];
#pragma unroll
    for (int mi = 0; mi < 4; mi++)
#pragma unroll
        for (int ni = 0; ni < 4; ni++)
#pragma unroll
            for (int q = 0; q < 4; q++) acc[mi][ni][q] = 0.f;

    const int r0c = tid >> 2, j0 = (tid & 3) * 8;
    const int r1c = (tid + 256) >> 2, j1 = ((tid + 256) & 3) * 8;

    auto issue = [&](int it) {
        __half* As = gsm + (it & 3) * GSTG_H;
        __half* Bs = As + 128 * GSTR;
        const int k0 = it * 32;
        cp_async16(&As[r0c * GSTR + j0], A + (size_t)(row0 + r0c) * GK + k0 + j0);
        cp_async16(&As[r1c * GSTR + j1], A + (size_t)(row0 + r1c) * GK + k0 + j1);
        cp_async16(&Bs[r0c * GSTR + j0], W + (size_t)(col0 + r0c) * GK + k0 + j0);
        cp_async16(&Bs[r1c * GSTR + j1], W + (size_t)(col0 + r1c) * GK + k0 + j1);
        cp_commit();
    };

    issue(0); issue(1); issue(2);

    const int aRow  = (lane & 7) + ((lane >> 3) & 1) * 8;
    const int aKoff = (lane >> 4) << 3;
    const int bRow  = ((lane >> 4) << 3) + (lane & 7);
    const int bKoff = ((lane >> 3) & 1) << 3;

    for (int it = 0; it < 32; it++) {
        if (it < 29) cp_wait<2>(); else cp_wait<0>();
        __syncthreads();

        if (it + 3 < 32) issue(it + 3);

        const uint32_t AcU = smU + ((it & 3) * GSTG_H) * 2;
        const uint32_t BcU = AcU + (128 * GSTR) * 2;

#pragma unroll
        for (int kks = 0; kks < 2; kks++) {
            unsigned af[4][4], bf[4][2];
#pragma unroll
            for (int mi = 0; mi < 4; mi++) {
                LDSM_X4(af[mi][0], af[mi][1], af[mi][2], af[mi][3],
                        AcU + (((wr * 64 + mi * 16 + aRow) * GSTR) + kks * 16 + aKoff) * 2);
            }
#pragma unroll
            for (int nb = 0; nb < 2; nb++) {
                unsigned m0, m1, m2, m3;
                LDSM_X4(m0, m1, m2, m3,
                        BcU + (((wc * 32 + nb * 16 + bRow) * GSTR) + kks * 16 + bKoff) * 2);
                bf[2 * nb][0] = m0; bf[2 * nb][1] = m1;
                bf[2 * nb + 1][0] = m2; bf[2 * nb + 1][1] = m3;
            }
#pragma unroll
            for (int mi = 0; mi < 4; mi++)
#pragma unroll
                for (int ni = 0; ni < 4; ni++)
                    mma_f16(acc[mi][ni], af[mi], bf[ni]);
        }
    }

    // epilogue
#pragma unroll
    for (int mi = 0; mi < 4; mi++) {
        const int r = row0 + wr * 64 + mi * 16 + grp;
#pragma unroll
        for (int ni = 0; ni < 4; ni++) {
            const int c = col0 + wc * 32 + ni * 8 + tig * 2;
            const float b0 = bias[c], b1 = bias[c + 1];
            const float v0 = acc[mi][ni][0] + b0;
            const float v1 = acc[mi][ni][1] + b1;
            const float v2 = acc[mi][ni][2] + b0;
            const float v3 = acc[mi][ni][3] + b1;
            if (OUT_FLOAT) {
                float* C = (float*)Cv;
                float2 w0 = { v0, v1 }, w1 = { v2, v3 };
                *(float2*)(C + (size_t)r * GN + c)       = w0;
                *(float2*)(C + (size_t)(r + 8) * GN + c) = w1;
            } else {
                __half* C = (__half*)Cv;
                *(unsigned*)(C + (size_t)r * GN + c)       = packh2(v0 * oscale, v1 * oscale);
                *(unsigned*)(C + (size_t)(r + 8) * GN + c) = packh2(v2 * oscale, v3 * oscale);
            }
        }
    }
}

// Fused Q/K/V projection GEMMs (blockIdx.z selects tensor). Q pre-scaled.
__global__ __launch_bounds__(256, 2) void gemm_qkv(
    const __half* X0, const __half* X1, const __half* X2,
    const __half* W0, const __half* W1, const __half* W2,
    const float* b0, const float* b1, const float* b2,
    __half* C0, __half* C1, __half* C2)
{
    extern __shared__ __half gsm[];
    const int z = blockIdx.z;
    const __half* A = (z == 0) ? X0 : (z == 1) ? X1 : X2;
    const __half* W = (z == 0) ? W0 : (z == 1) ? W1 : W2;
    const float*  b = (z == 0) ? b0 : (z == 1) ? b1 : b2;
    __half*       C = (z == 0) ? C0 : (z == 1) ? C1 : C2;
    const float oscale = (z == 0) ? SCALE_LOG2E : 1.0f;
    gemm_body<false>(A, W, b, C, gsm, blockIdx.y * 128, blockIdx.x * 128, oscale);
}

// Output projection GEMM (fp32 out)
__global__ __launch_bounds__(256, 2) void gemm_wo(
    const __half* __restrict__ A, const __half* __restrict__ W,
    const float* __restrict__ bias, float* __restrict__ C)
{
    extern __shared__ __half gsm[];
    gemm_body<true>(A, W, bias, C, gsm, blockIdx.y * 128, blockIdx.x * 128, 1.0f);
}

// ---------------------------------------------------------------------------
// FP16 causal flash attention, FA2-style (exp2 domain, Q pre-scaled).
// BM=128 (16 q-rows per warp), BN=64, 8 warps, 4-stage cp.async K/V,
// single barrier per tile. P computed with ex2.approx.f16x2 -> direct A-frags.
// ---------------------------------------------------------------------------
#define HSTR    72                          // halves per smem row
#define KV_H    (64 * HSTR)                 // halves per matrix per stage
#define KVSTG_B (2 * KV_H * 2)              // bytes per stage (K+V) = 18432
#define ATT_SMEM (4 * KVSTG_B)              // 73728 bytes

__global__ __launch_bounds__(256, 2) void attn_f16(
    const __half* __restrict__ Q,
    const __half* __restrict__ K,
    const __half* __restrict__ V,
    __half* __restrict__ O)
{
    extern __shared__ __half hsm[];
    const uint32_t smU = (uint32_t)__cvta_generic_to_shared(hsm);

    const int tid  = threadIdx.x;
    const int lane = tid & 31;
    const int wid  = tid >> 5;
    const int tig  = lane & 3;
    const int grp  = lane >> 2;

    const int qi = (gridDim.x - 1) - blockIdx.x;   // heavy blocks first
    const int h  = blockIdx.y;
    const int b  = blockIdx.z;

    const int ktmax = 2 * qi + 1;

    // copy mapping (64-row tile): row = tid>>2, piece halves (tid&3)*8 and +32
    const int c0r = tid >> 2;
    const int j0h = (tid & 3) * 8;

    const __half* Kbase = K + (size_t)b * SEQ * HID + h * HD;
    const __half* Vbase = V + (size_t)b * SEQ * HID + h * HD;

    // stage = slot index (0..3); kt = tile whose data is loaded
    auto issue = [&](int stage, int kt) {
        __half* Ks = hsm + stage * (2 * KV_H);
        __half* Vs = Ks + KV_H;
        const __half* Kb = Kbase + (size_t)kt * 64 * HID;
        const __half* Vb = Vbase + (size_t)kt * 64 * HID;
        cp_async16(&Ks[c0r * HSTR + j0h],      Kb + (size_t)c0r * HID + j0h);
        cp_async16(&Ks[c0r * HSTR + j0h + 32], Kb + (size_t)c0r * HID + j0h + 32);
        cp_async16(&Vs[c0r * HSTR + j0h],      Vb + (size_t)c0r * HID + j0h);
        cp_async16(&Vs[c0r * HSTR + j0h + 32], Vb + (size_t)c0r * HID + j0h + 32);
        cp_commit();
    };

    // prologue: fill 3 stages (tile index clamped; dup data never read)
    issue(0, 0);
    issue(1, (1 <= ktmax) ? 1 : ktmax);
    issue(2, (2 <= ktmax) ? 2 : ktmax);

    // Q fragments: direct LDG (rows warp-owned); Q pre-scaled by 0.125*log2e
    const int rowlo = qi * 128 + wid * 16 + grp;
    const __half* Qp = Q + ((size_t)b * SEQ + rowlo) * HID + h * HD;
    unsigned qf[4][4];
#pragma unroll
    for (int kk = 0; kk < 4; kk++) {
        qf[kk][0] = *(const unsigned*)(Qp + kk * 16 + tig * 2);
        qf[kk][1] = *(const unsigned*)(Qp + (size_t)8 * HID + kk * 16 + tig * 2);
        qf[kk][2] = *(const unsigned*)(Qp + kk * 16 + 8 + tig * 2);
        qf[kk][3] = *(const unsigned*)(Qp + (size_t)8 * HID + kk * 16 + 8 + tig * 2);
    }

    // ldmatrix per-lane address components
    const int kRow  = ((lane >> 4) << 3) + (lane & 7);
    const int kKoff = ((lane >> 3) & 1) << 3;
    const int vRow  = lane & 15;
    const int vD    = (lane >> 4) << 3;

    float m_i[2] = { -1e30f, -1e30f };
    float l_i[2] = { 0.f, 0.f };
    float o[8][4];
#pragma unroll
    for (int ni = 0; ni < 8; ni++)
#pragma unroll
        for (int q = 0; q < 4; q++) o[ni][q] = 0.f;

    for (int kt = 0; kt <= ktmax; kt++) {
        if (kt + 2 <= ktmax) cp_wait<2>(); else cp_wait<0>();
        __syncthreads();   // single barrier: stage kt ready; stage kt-1 free

        if (kt + 3 <= ktmax) issue((kt + 3) & 3, kt + 3);

        const uint32_t KsU = smU + (kt & 3) * KVSTG_B;
        const uint32_t VsU = KsU + KV_H * 2;

        // ---- S = Q K^T (16 x 64 per warp), already in log2 domain ----
        float s[8][4];
#pragma unroll
        for (int ni = 0; ni < 8; ni++)
#pragma unroll
            for (int q = 0; q < 4; q++) s[ni][q] = 0.f;

#pragma unroll
        for (int kk = 0; kk < 4; kk++) {
#pragma unroll
            for (int nib = 0; nib < 8; nib += 2) {
                unsigned m0, m1, m2, m3;
                LDSM_X4(m0, m1, m2, m3,
                        KsU + ((nib * 8 + kRow) * HSTR + kk * 16 + kKoff) * 2);
                unsigned bf0[2] = { m0, m1 };
                unsigned bf1[2] = { m2, m3 };
                mma_f16(s[nib],     qf[kk], bf0);
                mma_f16(s[nib + 1], qf[kk], bf1);
            }
        }

        // causal mask (diagonal tiles only)
        if (kt >= 2 * qi) {
#pragma unroll
            for (int ni = 0; ni < 8; ni++) {
                const int c0 = kt * 64 + ni * 8 + tig * 2;
#pragma unroll
                for (int q = 0; q < 4; q++) {
                    const int row = (q < 2) ? rowlo : rowlo + 8;
                    const int col = c0 + (q & 1);
                    if (col > row) s[ni][q] = -1e30f;
                }
            }
        }

        // online softmax: exp via ex2.approx.f16x2, results ARE the A-frags
        unsigned ep[8][2];
#pragma unroll
        for (int r = 0; r < 2; r++) {
            const int q0 = 2 * r, q1 = 2 * r + 1;
            float mx = -1e30f;
#pragma unroll
            for (int ni = 0; ni < 8; ni++)
                mx = fmaxf(mx, fmaxf(s[ni][q0], s[ni][q1]));
            mx = fmaxf(mx, __shfl_xor_sync(0xffffffffu, mx, 1));
            mx = fmaxf(mx, __shfl_xor_sync(0xffffffffu, mx, 2));
            const float m_new = fmaxf(m_i[r], mx);
            const float al    = exp2f(m_i[r] - m_new);
#pragma unroll
            for (int ni = 0; ni < 8; ni++)
                ep[ni][r] = ex2h2(packh2(s[ni][q0] - m_new, s[ni][q1] - m_new));
            // half2 tree sum -> f32
            unsigned t0 = hadd2u(ep[0][r], ep[1][r]);
            unsigned t1 = hadd2u(ep[2][r], ep[3][r]);
            unsigned t2 = hadd2u(ep[4][r], ep[5][r]);
            unsigned t3 = hadd2u(ep[6][r], ep[7][r]);
            unsigned tt = hadd2u(hadd2u(t0, t1), hadd2u(t2, t3));
            float2 fs = __half22float2(*reinterpret_cast<__half2*>(&tt));
            float sum = fs.x + fs.y;
            sum += __shfl_xor_sync(0xffffffffu, sum, 1);
            sum += __shfl_xor_sync(0xffffffffu, sum, 2);
            l_i[r] = l_i[r] * al + sum;
            m_i[r] = m_new;
#pragma unroll
            for (int ni = 0; ni < 8; ni++) {
                o[ni][q0] *= al;
                o[ni][q1] *= al;
            }
        }

        // ---- O += P V (P frags from ep, V via ldmatrix.trans) ----
#pragma unroll
        for (int kkm = 0; kkm < 4; kkm++) {
            unsigned a[4];
            a[0] = ep[2 * kkm][0];
            a[1] = ep[2 * kkm][1];
            a[2] = ep[2 * kkm + 1][0];
            a[3] = ep[2 * kkm + 1][1];
#pragma unroll
            for (int nidb = 0; nidb < 8; nidb += 2) {
                unsigned m0, m1, m2, m3;
                LDSM_X4T(m0, m1, m2, m3,
                         VsU + ((kkm * 16 + vRow) * HSTR + nidb * 8 + vD) * 2);
                unsigned bf0[2] = { m0, m1 };
                unsigned bf1[2] = { m2, m3 };
                mma_f16(o[nidb],     a, bf0);
                mma_f16(o[nidb + 1], a, bf1);
            }
        }
    }

    // epilogue: divide by l, store fp16
    const float inv0 = 1.f / l_i[0];
    const float inv1 = 1.f / l_i[1];
    __half* Ob = O + ((size_t)b * SEQ + rowlo) * HID + h * HD;
#pragma unroll
    for (int ni = 0; ni < 8; ni++) {
        const int d = ni * 8 + tig * 2;
        *(unsigned*)(Ob + d)                    = packh2(o[ni][0] * inv0, o[ni][1] * inv0);
        *(unsigned*)(Ob + (size_t)8 * HID + d)  = packh2(o[ni][2] * inv1, o[ni][3] * inv1);
    }
}

// ---------------------------------------------------------------------------
extern "C" void kernel_launch(void* const* d_in, const int* in_sizes, int n_in,
                              void* d_out, int out_size)
{
    const float* query = (const float*)d_in[0];
    const float* key   = (const float*)d_in[1];
    const float* val   = (const float*)d_in[2];
    // d_in[3] = attn_mask (tril causal) — implemented directly in attn_f16
    const float* Wq = (const float*)d_in[4];
    const float* bq = (const float*)d_in[5];
    const float* Wk = (const float*)d_in[6];
    const float* bk = (const float*)d_in[7];
    const float* Wv = (const float*)d_in[8];
    const float* bv = (const float*)d_in[9];
    const float* Wo = (const float*)d_in[10];
    const float* bo = (const float*)d_in[11];
    float* out = (float*)d_out;

    void *pQ, *pK, *pV, *pAO, *pXq, *pXk, *pXv, *pWq, *pWk, *pWv, *pWo;
    cudaGetSymbolAddress(&pQ,  g_Q);
    cudaGetSymbolAddress(&pK,  g_K);
    cudaGetSymbolAddress(&pV,  g_V);
    cudaGetSymbolAddress(&pAO, g_AO);
    cudaGetSymbolAddress(&pXq, g_Xq);
    cudaGetSymbolAddress(&pXk, g_Xk);
    cudaGetSymbolAddress(&pXv, g_Xv);
    cudaGetSymbolAddress(&pWq, g_Wq);
    cudaGetSymbolAddress(&pWk, g_Wk);
    cudaGetSymbolAddress(&pWv, g_Wv);
    cudaGetSymbolAddress(&pWo, g_Wo);

    cudaFuncSetAttribute(gemm_qkv,
                         cudaFuncAttributeMaxDynamicSharedMemorySize, GEMM_SMEM);
    cudaFuncSetAttribute(gemm_wo,
                         cudaFuncAttributeMaxDynamicSharedMemorySize, GEMM_SMEM);
    cudaFuncSetAttribute(attn_f16,
                         cudaFuncAttributeMaxDynamicSharedMemorySize, ATT_SMEM);

    // pre-pass: convert inputs to fp16 (2 fused launches)
    const int nX8 = MTOT * HID / 8;
    const int nW8 = HID * HID / 8;
    {
        dim3 g3((nX8 + 255) / 256, 3);
        cvt_h3<<<g3, 256>>>(query, key, val,
                            (__half*)pXq, (__half*)pXk, (__half*)pXv, nX8);
        dim3 g4((nW8 + 255) / 256, 4);
        cvt_h4<<<g4, 256>>>(Wq, Wk, Wv, Wo,
                            (__half*)pWq, (__half*)pWk, (__half*)pWv, (__half*)pWo, nW8);
    }

    const dim3 gqkv(GN / 128, MTOT / 128, 3);  // (8, 64, 3)
    gemm_qkv<<<gqkv, 256, GEMM_SMEM>>>(
        (const __half*)pXq, (const __half*)pXk, (const __half*)pXv,
        (const __half*)pWq, (const __half*)pWk, (const __half*)pWv,
        bq, bk, bv,
        (__half*)pQ, (__half*)pK, (__half*)pV);

    const dim3 agrid(SEQ / 128, NH, BATCH);     // (16, 16, 4)
    attn_f16<<<agrid, 256, ATT_SMEM>>>((const __half*)pQ, (const __half*)pK,
                                       (const __half*)pV, (__half*)pAO);

    const dim3 gwo(GN / 128, MTOT / 128);       // (8, 64)
    gemm_wo<<<gwo, 256, GEMM_SMEM>>>((const __half*)pAO, (const __half*)pWo, bo, out);
}